// round 13
// baseline (speedup 1.0000x reference)
#include <cuda_runtime.h>
#include <cuda_fp16.h>
#include <math.h>
#include <stdint.h>

// Problem constants
#define BB 64
#define KK 512
#define MM 512
#define DD 256
#define NI 15
#define MI 3
#define RQ (BB*KK)              // 32768
#define RTOT (2*RQ)             // 65536
#define PLANE ((size_t)KK*MM)
#define TOTE ((size_t)BB*PLANE) // 16777216
#define PSZ ((size_t)RTOT*DD)

// ---------------- device scratch (static; no allocation) ----------------
__device__ __half g_Xh[PSZ], g_Xl[PSZ];
__device__ __half g_Hh[PSZ], g_Hl[PSZ];
__device__ __half g_Ph[PSZ], g_Pl[PSZ];
__device__ __half g_W1h[DD*DD], g_W1l[DD*DD];
__device__ __half g_W2h[DD*DD], g_W2l[DD*DD];
__device__ float g_E[TOTE];
__device__ float g_q2[RQ], g_r2[RQ];
__device__ float g_logmu[RQ], g_lognu[RQ], g_rowRef[RQ];
__device__ float g_la[RQ], g_lb[RQ];
__device__ float g_cvec[BB];

// ---------------- fast exp on FMA pipe ----------------
__device__ __forceinline__ float fexp(float x) {
    x = fminf(fmaxf(x, -87.0f), 88.0f);
    const float L2E    = 1.4426950408889634f;
    const float L2E_LO = 1.9259629911e-8f;
    float t  = fmaf(x, L2E, 12582912.0f);
    float kf = t - 12582912.0f;
    float r  = fmaf(x, L2E, -kf);
    r = fmaf(x, L2E_LO, r);
    float p = 1.5403530e-4f;
    p = fmaf(p, r, 1.33335581e-3f);
    p = fmaf(p, r, 9.61812911e-3f);
    p = fmaf(p, r, 5.55041087e-2f);
    p = fmaf(p, r, 2.40226507e-1f);
    p = fmaf(p, r, 6.93147182e-1f);
    p = fmaf(p, r, 1.0f);
    int ei = (int)kf;
    float s = __int_as_float((ei + 127) << 23);
    return p * s;
}

// ---------------- small PTX helpers ----------------
__device__ __forceinline__ uint32_t smem_u32(const void* p) {
    return (uint32_t)__cvta_generic_to_shared(p);
}
__device__ __forceinline__ void cpasync16(uint32_t s, const void* g) {
    asm volatile("cp.async.cg.shared.global [%0], [%1], 16;" :: "r"(s), "l"(g));
}
#define CP_COMMIT asm volatile("cp.async.commit_group;" ::: "memory")
#define CP_WAIT0  asm volatile("cp.async.wait_group 0;" ::: "memory")
#define CP_WAIT1  asm volatile("cp.async.wait_group 1;" ::: "memory")

__device__ __forceinline__ float dsmem_ld_f(uint32_t saddr, uint32_t rank) {
    uint32_t ra; float v;
    asm volatile("mapa.shared::cluster.u32 %0, %1, %2;" : "=r"(ra) : "r"(saddr), "r"(rank));
    asm volatile("ld.shared::cluster.f32 %0, [%1];" : "=f"(v) : "r"(ra));
    return v;
}
__device__ __forceinline__ void cluster_sync_() {
    asm volatile("barrier.cluster.arrive.aligned;" ::: "memory");
    asm volatile("barrier.cluster.wait.aligned;" ::: "memory");
}

__device__ __forceinline__ void ldsm4(uint32_t& r0, uint32_t& r1, uint32_t& r2,
                                      uint32_t& r3, uint32_t addr) {
    asm volatile("ldmatrix.sync.aligned.m8n8.x4.shared.b16 {%0,%1,%2,%3}, [%4];"
                 : "=r"(r0), "=r"(r1), "=r"(r2), "=r"(r3) : "r"(addr));
}
__device__ __forceinline__ void mma16816h(float* d, const uint32_t* a,
                                          uint32_t b0, uint32_t b1) {
    asm volatile(
        "mma.sync.aligned.m16n8k16.row.col.f32.f16.f16.f32 "
        "{%0,%1,%2,%3}, {%4,%5,%6,%7}, {%8,%9}, {%0,%1,%2,%3};"
        : "+f"(d[0]), "+f"(d[1]), "+f"(d[2]), "+f"(d[3])
        : "r"(a[0]), "r"(a[1]), "r"(a[2]), "r"(a[3]), "r"(b0), "r"(b1));
}

// ---------------- fp32 -> 2x fp16 split ----------------
__global__ void __launch_bounds__(256) split2_kernel(const float* __restrict__ x,
                                                     __half* __restrict__ o1,
                                                     __half* __restrict__ o2,
                                                     int n4) {
    int i = blockIdx.x * 256 + threadIdx.x;
    if (i >= n4) return;
    float4 v = ((const float4*)x)[i];
    float vv[4] = {v.x, v.y, v.z, v.w};
    unsigned short a[4], b[4];
#pragma unroll
    for (int j = 0; j < 4; j++) {
        __half h = __float2half_rn(vv[j]);
        float r1 = vv[j] - __half2float(h);
        __half l = __float2half_rn(r1);
        a[j] = *(unsigned short*)&h; b[j] = *(unsigned short*)&l;
    }
    *(uint2*)&o1[(size_t)i * 4] = *(uint2*)a;
    *(uint2*)&o2[(size_t)i * 4] = *(uint2*)b;
}

// ============================================================================
// fp16x2 tensor-core GEMM (Markidis 3-product). Same as R12 (passing).
// ============================================================================
#define STG_SZ 24576
#define DYN_SZ 67584
__global__ void __launch_bounds__(512) gemm_mma(
    const __half* __restrict__ Ah, const __half* __restrict__ Al,
    const __half* __restrict__ Bh, const __half* __restrict__ Bl,
    const float* __restrict__ bias,
    __half* __restrict__ O1, __half* __restrict__ O2,
    float* __restrict__ Cout, int mode)
{
    extern __shared__ char dynsmem[];
    uint32_t sbase = smem_u32(dynsmem);
    int t = threadIdx.x;
    int wid = t >> 5, lane = t & 31;
    int wm = wid >> 3, wn = wid & 7;

    int arow0, brow0, m0;
    if (mode < 2) {
        arow0 = blockIdx.x * 128; brow0 = blockIdx.y * 128; m0 = arow0;
    } else {
        arow0 = RQ + blockIdx.z * 512 + blockIdx.x * 128;
        brow0 = blockIdx.z * 512 + blockIdx.y * 128;
        m0 = blockIdx.x * 128;
    }

    const __half* srcp[2];
    uint32_t dstoff[2];
#pragma unroll
    for (int j = 0; j < 2; j++) {
        int idx = t + 512 * j;
        int arr = idx >> 8;
        int rem = idx & 255;
        int row = rem >> 1, seg = rem & 1;
        const __half* pl = (arr == 0) ? Ah : (arr == 1) ? Al : (arr == 2) ? Bh : Bl;
        int grow = ((arr < 2) ? arow0 : brow0) + row;
        srcp[j] = pl + (size_t)grow * DD + seg * 8;
        dstoff[j] = (uint32_t)(arr * 6144 + row * 48 + seg * 16);
    }

    float acc[4][2][4];
#pragma unroll
    for (int mt = 0; mt < 4; mt++)
#pragma unroll
        for (int nt = 0; nt < 2; nt++)
#pragma unroll
            for (int v = 0; v < 4; v++) acc[mt][nt][v] = 0.f;

#pragma unroll
    for (int j = 0; j < 2; j++) cpasync16(sbase + dstoff[j], srcp[j]);
    CP_COMMIT;

    uint32_t aAddrBase = (uint32_t)((wm * 64 + (lane & 15)) * 48 + ((lane >> 4) & 1) * 16);
    uint32_t bAddrBase = (uint32_t)(12288 +
        (wn * 16 + (lane & 7) + ((lane >> 4) & 1) * 8) * 48 + ((lane >> 3) & 1) * 16);

#pragma unroll 1
    for (int kc = 0; kc < 16; kc++) {
        if (kc < 15) {
            uint32_t sdst = sbase + ((kc + 1) & 1) * STG_SZ;
#pragma unroll
            for (int j = 0; j < 2; j++)
                cpasync16(sdst + dstoff[j], srcp[j] + (kc + 1) * 16);
            CP_COMMIT;
            CP_WAIT1;
        } else {
            CP_WAIT0;
        }
        __syncthreads();

        uint32_t stg = sbase + (kc & 1) * STG_SZ;
        uint32_t bh[4], bl[4];
        ldsm4(bh[0], bh[1], bh[2], bh[3], stg + bAddrBase);
        ldsm4(bl[0], bl[1], bl[2], bl[3], stg + bAddrBase + 6144);

#pragma unroll
        for (int mt = 0; mt < 4; mt++) {
            uint32_t a_h[4], a_l[4];
            uint32_t aa = stg + aAddrBase + (uint32_t)(mt * 16 * 48);
            ldsm4(a_h[0], a_h[1], a_h[2], a_h[3], aa);
            ldsm4(a_l[0], a_l[1], a_l[2], a_l[3], aa + 6144);
#pragma unroll
            for (int nt = 0; nt < 2; nt++) {
                float* d = acc[mt][nt];
                mma16816h(d, a_h, bh[nt * 2], bh[nt * 2 + 1]);
                mma16816h(d, a_h, bl[nt * 2], bl[nt * 2 + 1]);
                mma16816h(d, a_l, bh[nt * 2], bh[nt * 2 + 1]);
            }
        }
        __syncthreads();
    }

    float* sT = (float*)dynsmem;
#pragma unroll
    for (int mt = 0; mt < 4; mt++)
#pragma unroll
        for (int nt = 0; nt < 2; nt++)
#pragma unroll
            for (int v = 0; v < 4; v++) {
                int n = wn * 16 + nt * 8 + (lane & 3) * 2 + (v & 1);
                int m = wm * 64 + mt * 16 + (lane >> 2) + ((v & 2) ? 8 : 0);
                sT[n * 132 + m] = acc[mt][nt][v];
            }
    __syncthreads();

#pragma unroll 1
    for (int rr = 0; rr < 8; rr++) {
        int n = wid * 8 + rr;
        float4 v4 = *(float4*)&sT[n * 132 + lane * 4];
        float vv[4] = {v4.x, v4.y, v4.z, v4.w};
        int gn = brow0 + n;
        if (mode < 2) {
            float nrm = 0.f;
            unsigned short h[4], lo[4];
#pragma unroll
            for (int j = 0; j < 4; j++) {
                float v = vv[j] + bias[m0 + lane * 4 + j];
                if (mode == 0) v = fmaxf(v, 0.f);
                else nrm += v * v;
                __half hh_ = __float2half_rn(v);
                float r1 = v - __half2float(hh_);
                __half ll_ = __float2half_rn(r1);
                h[j] = *(unsigned short*)&hh_;
                lo[j] = *(unsigned short*)&ll_;
            }
            size_t ob = (size_t)gn * DD + m0 + lane * 4;
            *(uint2*)&O1[ob] = *(uint2*)h;
            *(uint2*)&O2[ob] = *(uint2*)lo;
            if (mode == 1) {
#pragma unroll
                for (int o = 16; o; o >>= 1) nrm += __shfl_xor_sync(~0u, nrm, o);
                if (lane == 0) {
                    if (gn < RQ) atomicAdd(&g_q2[gn], nrm);
                    else         atomicAdd(&g_r2[gn - RQ], nrm);
                }
            }
        } else {
            float q2v = g_q2[gn];
            int rbase = blockIdx.z * 512 + m0 + lane * 4;
            float4 o;
            o.x = sqrtf(fmaxf(q2v + g_r2[rbase + 0] - 2.f * vv[0], 1e-6f));
            o.y = sqrtf(fmaxf(q2v + g_r2[rbase + 1] - 2.f * vv[1], 1e-6f));
            o.z = sqrtf(fmaxf(q2v + g_r2[rbase + 2] - 2.f * vv[2], 1e-6f));
            o.w = sqrtf(fmaxf(q2v + g_r2[rbase + 3] - 2.f * vv[3], 1e-6f));
            *(float4*)&Cout[(size_t)gn * 512 + m0 + lane * 4] = o;
        }
    }
}

// ---------------- prep: logmu/lognu, zero buffers ----------------
__global__ void __launch_bounds__(512) prep_kernel(const float* __restrict__ mq,
                                                   const float* __restrict__ mr) {
    __shared__ float red[512];
    int b = blockIdx.x, t = threadIdx.x;
    float vq = mq[b * 512 + t];
    red[t] = vq; __syncthreads();
    for (int s = 256; s; s >>= 1) { if (t < s) red[t] += red[t + s]; __syncthreads(); }
    float smq = red[0]; __syncthreads();
    g_logmu[b * 512 + t] = logf(fmaxf(vq / (smq + 1e-8f), 1e-8f));

    float vr = mr[b * 512 + t];
    red[t] = vr; __syncthreads();
    for (int s = 256; s; s >>= 1) { if (t < s) red[t] += red[t + s]; __syncthreads(); }
    float smr = red[0]; __syncthreads();
    g_lognu[b * 512 + t] = logf(fmaxf(vr / (smr + 1e-8f), 1e-8f));

    g_q2[b * 512 + t] = 0.f;
    g_r2[b * 512 + t] = 0.f;
    if (t == 0) g_cvec[b] = 0.f;
}

// ---------------- build E = exp(-20C + lognu - rowmax) ----------------
__global__ void __launch_bounds__(256) ebuild_kernel(const float* __restrict__ C) {
    int wid = threadIdx.x >> 5, lane = threadIdx.x & 31;
    int gid = blockIdx.x * 8 + wid;
    int b = gid >> 9;
    size_t base = (size_t)gid * 512;
    const float4* Crow = (const float4*)(C + base);
    const float4* Nu   = (const float4*)(g_lognu + (size_t)b * 512);
    float4 v4[4];
    float mx = -1e30f;
#pragma unroll
    for (int c = 0; c < 4; c++) {
        float4 cc = Crow[lane + 32 * c];
        float4 nu = Nu[lane + 32 * c];
        float4 v;
        v.x = fmaf(cc.x, -20.f, nu.x);
        v.y = fmaf(cc.y, -20.f, nu.y);
        v.z = fmaf(cc.z, -20.f, nu.z);
        v.w = fmaf(cc.w, -20.f, nu.w);
        v4[c] = v;
        mx = fmaxf(mx, fmaxf(fmaxf(v.x, v.y), fmaxf(v.z, v.w)));
    }
#pragma unroll
    for (int o = 16; o; o >>= 1) mx = fmaxf(mx, __shfl_xor_sync(~0u, mx, o));
    float4* Erow = (float4*)(g_E + base);
#pragma unroll
    for (int c = 0; c < 4; c++) {
        float4 e;
        e.x = fexp(v4[c].x - mx); e.y = fexp(v4[c].y - mx);
        e.z = fexp(v4[c].z - mx); e.w = fexp(v4[c].w - mx);
        Erow[lane + 32 * c] = e;
    }
    if (lane == 0) g_rowRef[gid] = mx;
}

// ============================================================================
// Fused Sinkhorn, single E-sweep per iteration (R12, passing).
// ============================================================================
__global__ void __launch_bounds__(256, 1) __cluster_dims__(4, 1, 1)
sinkhorn_cluster() {
    __shared__ __align__(16) float s_vb[512];
    __shared__ float s_partial[512];
    __shared__ float s_lb[512];
    __shared__ float s_g[128];
    __shared__ float s_rc[128];
    __shared__ float s_red[256];
    __shared__ float s_locmax;

    int bat = blockIdx.x >> 2;
    int rank = blockIdx.x & 3;
    int t = threadIdx.x;
    int wid = t >> 5, lane = t & 31;
    int rowbase = bat * 512 + rank * 128;
    const float* Eb = g_E + (size_t)rowbase * 512;

    if (t < 128) s_rc[t] = g_logmu[rowbase + t] + g_rowRef[rowbase + t];
    s_lb[t] = 0.f; s_lb[t + 256] = 0.f;
    __syncthreads();

    float sa_prev = 0.f;

    for (int it = 0; it < NI; it++) {
        s_red[t] = fmaxf(s_lb[t], s_lb[t + 256]);
        __syncthreads();
        for (int s = 128; s; s >>= 1) { if (t < s) s_red[t] = fmaxf(s_red[t], s_red[t + s]); __syncthreads(); }
        float sb = s_red[0];
        __syncthreads();
        s_vb[t]       = fexp(s_lb[t] - sb);
        s_vb[t + 256] = fexp(s_lb[t + 256] - sb);
        s_partial[t] = 0.f; s_partial[t + 256] = 0.f;
        __syncthreads();

        float colacc[16];
#pragma unroll
        for (int j = 0; j < 16; j++) colacc[j] = 0.f;
        float gmaxloc = -1e30f;

#pragma unroll 1
        for (int rr = wid; rr < 128; rr += 8) {
            const float4* Er = (const float4*)(Eb + (size_t)rr * 512);
            const float4* V  = (const float4*)s_vb;
            float4 ev[4];
            float acc = 0.f;
#pragma unroll
            for (int c = 0; c < 4; c++) {
                ev[c] = Er[lane + 32 * c];
                float4 v = V[lane + 32 * c];
                acc += ev[c].x * v.x + ev[c].y * v.y + ev[c].z * v.z + ev[c].w * v.w;
            }
#pragma unroll
            for (int o = 16; o; o >>= 1) acc += __shfl_xor_sync(~0u, acc, o);
            float g = -(sb + logf(fmaxf(acc, 1e-35f)));
            if (lane == 0) s_g[rr] = g;
            gmaxloc = fmaxf(gmaxloc, g);
            float wa = fexp(g - sa_prev);
#pragma unroll
            for (int c = 0; c < 4; c++) {
                colacc[c * 4 + 0] = fmaf(ev[c].x, wa, colacc[c * 4 + 0]);
                colacc[c * 4 + 1] = fmaf(ev[c].y, wa, colacc[c * 4 + 1]);
                colacc[c * 4 + 2] = fmaf(ev[c].z, wa, colacc[c * 4 + 2]);
                colacc[c * 4 + 3] = fmaf(ev[c].w, wa, colacc[c * 4 + 3]);
            }
        }
#pragma unroll
        for (int c = 0; c < 4; c++) {
            int m = (lane + 32 * c) * 4;
            atomicAdd(&s_partial[m + 0], colacc[c * 4 + 0]);
            atomicAdd(&s_partial[m + 1], colacc[c * 4 + 1]);
            atomicAdd(&s_partial[m + 2], colacc[c * 4 + 2]);
            atomicAdd(&s_partial[m + 3], colacc[c * 4 + 3]);
        }
        s_red[t] = gmaxloc;
        __syncthreads();
        for (int s = 128; s; s >>= 1) { if (t < s) s_red[t] = fmaxf(s_red[t], s_red[t + s]); __syncthreads(); }
        if (t == 0) s_locmax = s_red[0];
        __syncthreads();
        cluster_sync_();   // publish partials + locmax

        float sa_new = -1e30f;
        uint32_t lmaddr = smem_u32(&s_locmax);
#pragma unroll
        for (int r = 0; r < 4; r++) sa_new = fmaxf(sa_new, dsmem_ld_f(lmaddr, r));

#pragma unroll
        for (int cg = 0; cg < 2; cg++) {
            int col = t + cg * 256;
            uint32_t pa = smem_u32(&s_partial[col]);
            float s = 0.f;
#pragma unroll
            for (int r = 0; r < 4; r++) s += dsmem_ld_f(pa, r);
            s_lb[col] = -(sa_prev + logf(fmaxf(s, 1e-35f)));
        }
        __syncthreads();
        cluster_sync_();   // remote reads done
        sa_prev = sa_new;
    }

    if (t < 128) g_la[rowbase + t] = s_g[t] - s_rc[t];
    if (rank == 0) {
        g_lb[bat * 512 + t]       = s_lb[t];
        g_lb[bat * 512 + 256 + t] = s_lb[t + 256];
    }
    cluster_sync_();
}

// ============================================================================
// Fused MI chain: cluster of 8 CTAs per batch, T plane resident in SMEM.
// Each CTA owns 64 rows (64*512*4 = 128KB dyn smem). One E read, one T write,
// one C read; all intermediates in smem. Colsums exchanged via DSMEM with the
// publish/consume double-sync protocol (as in sinkhorn_cluster).
// ============================================================================
#define MI_DYN (64*512*4)
__global__ void __launch_bounds__(256, 1) __cluster_dims__(8, 1, 1)
mi_cluster(float* __restrict__ T, const float* __restrict__ C) {
    extern __shared__ float sT[];            // [64][512]
    __shared__ float s_part[512];
    __shared__ float s_inv[512];
    __shared__ float s_rb[512];
    __shared__ float s_red[8];

    int bat = blockIdx.x >> 3;
    int rank = blockIdx.x & 7;
    int t = threadIdx.x, wid = t >> 5, lane = t & 31;
    int rowbase = bat * 512 + rank * 64;

    s_rb[t]       = fexp(g_lb[bat * 512 + t]);
    s_rb[t + 256] = fexp(g_lb[bat * 512 + 256 + t]);
    s_part[t] = 0.f; s_part[t + 256] = 0.f;
    __syncthreads();

    float colacc[16];
#pragma unroll
    for (int j = 0; j < 16; j++) colacc[j] = 0.f;

    // ---- pass 0: T0 = rownorm((E*ra*rb)^2) into smem; colsum partials ----
    const float* Eb = g_E + (size_t)rowbase * 512;
#pragma unroll 1
    for (int rr = wid; rr < 64; rr += 8) {
        int k = rowbase + rr;
        float ra = fexp(g_logmu[k] + g_rowRef[k] + g_la[k]);
        const float4* Er = (const float4*)(Eb + (size_t)rr * 512);
        float4* Tr = (float4*)(sT + rr * 512);
        float4 xv[4];
        float rs = 0.f;
#pragma unroll
        for (int c = 0; c < 4; c++) {
            float4 e  = Er[lane + 32 * c];
            float4 r4 = ((const float4*)s_rb)[lane + 32 * c];
            float4 x;
            x.x = e.x * ra * r4.x; x.y = e.y * ra * r4.y;
            x.z = e.z * ra * r4.z; x.w = e.w * ra * r4.w;
            x.x *= x.x; x.y *= x.y; x.z *= x.z; x.w *= x.w;
            xv[c] = x;
            rs += x.x + x.y + x.z + x.w;
        }
#pragma unroll
        for (int o = 16; o; o >>= 1) rs += __shfl_xor_sync(~0u, rs, o);
        float inv = 1.0f / (rs + 1e-8f);
#pragma unroll
        for (int c = 0; c < 4; c++) {
            float4 x = xv[c];
            x.x *= inv; x.y *= inv; x.z *= inv; x.w *= inv;
            Tr[lane + 32 * c] = x;
            colacc[c * 4 + 0] += x.x; colacc[c * 4 + 1] += x.y;
            colacc[c * 4 + 2] += x.z; colacc[c * 4 + 3] += x.w;
        }
    }
#pragma unroll
    for (int c = 0; c < 4; c++) {
        int m = (lane + 32 * c) * 4;
        atomicAdd(&s_part[m + 0], colacc[c * 4 + 0]);
        atomicAdd(&s_part[m + 1], colacc[c * 4 + 1]);
        atomicAdd(&s_part[m + 2], colacc[c * 4 + 2]);
        atomicAdd(&s_part[m + 3], colacc[c * 4 + 3]);
    }
    __syncthreads();
    cluster_sync_();                 // publish partials
#pragma unroll
    for (int cg = 0; cg < 2; cg++) {
        int col = t + cg * 256;
        uint32_t pa = smem_u32(&s_part[col]);
        float s = 0.f;
#pragma unroll
        for (int r = 0; r < 8; r++) s += dsmem_ld_f(pa, r);
        s_inv[col] = 1.0f / (s + 1e-8f);
    }
    __syncthreads();
    cluster_sync_();                 // remote reads done

    // ---- passes 1..2 fully in smem ----
#pragma unroll 1
    for (int it = 1; it <= 2; it++) {
        s_part[t] = 0.f; s_part[t + 256] = 0.f;
#pragma unroll
        for (int j = 0; j < 16; j++) colacc[j] = 0.f;
        __syncthreads();
#pragma unroll 1
        for (int rr = wid; rr < 64; rr += 8) {
            float4* Tr = (float4*)(sT + rr * 512);
            float4 xv[4];
            float rs = 0.f;
#pragma unroll
            for (int c = 0; c < 4; c++) {
                float4 x  = Tr[lane + 32 * c];
                float4 iv = ((const float4*)s_inv)[lane + 32 * c];
                x.x *= iv.x; x.y *= iv.y; x.z *= iv.z; x.w *= iv.w;
                x.x *= x.x; x.y *= x.y; x.z *= x.z; x.w *= x.w;
                xv[c] = x;
                rs += x.x + x.y + x.z + x.w;
            }
#pragma unroll
            for (int o = 16; o; o >>= 1) rs += __shfl_xor_sync(~0u, rs, o);
            float rinv = 1.0f / (rs + 1e-8f);
#pragma unroll
            for (int c = 0; c < 4; c++) {
                float4 x = xv[c];
                x.x *= rinv; x.y *= rinv; x.z *= rinv; x.w *= rinv;
                Tr[lane + 32 * c] = x;
                colacc[c * 4 + 0] += x.x; colacc[c * 4 + 1] += x.y;
                colacc[c * 4 + 2] += x.z; colacc[c * 4 + 3] += x.w;
            }
        }
#pragma unroll
        for (int c = 0; c < 4; c++) {
            int m = (lane + 32 * c) * 4;
            atomicAdd(&s_part[m + 0], colacc[c * 4 + 0]);
            atomicAdd(&s_part[m + 1], colacc[c * 4 + 1]);
            atomicAdd(&s_part[m + 2], colacc[c * 4 + 2]);
            atomicAdd(&s_part[m + 3], colacc[c * 4 + 3]);
        }
        __syncthreads();
        cluster_sync_();             // publish partials
#pragma unroll
        for (int cg = 0; cg < 2; cg++) {
            int col = t + cg * 256;
            uint32_t pa = smem_u32(&s_part[col]);
            float s = 0.f;
#pragma unroll
            for (int r = 0; r < 8; r++) s += dsmem_ld_f(pa, r);
            s_inv[col] = 1.0f / (s + 1e-8f);
        }
        __syncthreads();
        cluster_sync_();             // remote reads done
    }

    // ---- final: T_out = T2 * s_inv; c += sum(T_out * C) ----
    const float* Cb = C + (size_t)rowbase * 512;
    float* Tg = T + (size_t)rowbase * 512;
    float cacc = 0.f;
#pragma unroll 1
    for (int rr = wid; rr < 64; rr += 8) {
        const float4* Tr = (const float4*)(sT + rr * 512);
        const float4* Cr = (const float4*)(Cb + (size_t)rr * 512);
        float4* Og = (float4*)(Tg + (size_t)rr * 512);
#pragma unroll
        for (int c = 0; c < 4; c++) {
            float4 x  = Tr[lane + 32 * c];
            float4 iv = ((const float4*)s_inv)[lane + 32 * c];
            x.x *= iv.x; x.y *= iv.y; x.z *= iv.z; x.w *= iv.w;
            Og[lane + 32 * c] = x;
            float4 cc = Cr[lane + 32 * c];
            cacc += x.x * cc.x + x.y * cc.y + x.z * cc.z + x.w * cc.w;
        }
    }
#pragma unroll
    for (int o = 16; o; o >>= 1) cacc += __shfl_xor_sync(~0u, cacc, o);
    if (lane == 0) s_red[wid] = cacc;
    __syncthreads();
    if (t == 0) {
        float s = 0.f;
#pragma unroll
        for (int w = 0; w < 8; w++) s += s_red[w];
        atomicAdd(&g_cvec[bat], s);
    }
}

// ---------------- finalize ----------------
__global__ void finalize_kernel(float* __restrict__ sim, float* __restrict__ outc) {
    int b = threadIdx.x;
    if (b < BB) {
        float c = g_cvec[b];
        outc[b] = c;
        sim[b] = 1.0f / (1.0f + expf(c));
    }
}

// ---------------- launch ----------------
extern "C" void kernel_launch(void* const* d_in, const int* in_sizes, int n_in,
                              void* d_out, int out_size) {
    const float* sq = (const float*)d_in[0];
    const float* sr = (const float*)d_in[1];
    const float* mq = (const float*)d_in[2];
    const float* mr = (const float*)d_in[3];
    const float* W1 = (const float*)d_in[4];
    const float* b1 = (const float*)d_in[5];
    const float* W2 = (const float*)d_in[6];
    const float* b2 = (const float*)d_in[7];

    float* out = (float*)d_out;
    float* out_sim = out;
    float* out_T   = out + BB;
    float* out_C   = out + BB + TOTE;
    float* out_c   = out + BB + 2 * TOTE;

    __half *Xh, *Xl, *Hh, *Hl, *Ph, *Pl, *W1h, *W1l, *W2h, *W2l;
    cudaGetSymbolAddress((void**)&Xh, g_Xh);  cudaGetSymbolAddress((void**)&Xl, g_Xl);
    cudaGetSymbolAddress((void**)&Hh, g_Hh);  cudaGetSymbolAddress((void**)&Hl, g_Hl);
    cudaGetSymbolAddress((void**)&Ph, g_Ph);  cudaGetSymbolAddress((void**)&Pl, g_Pl);
    cudaGetSymbolAddress((void**)&W1h, g_W1h); cudaGetSymbolAddress((void**)&W1l, g_W1l);
    cudaGetSymbolAddress((void**)&W2h, g_W2h); cudaGetSymbolAddress((void**)&W2l, g_W2l);

    cudaFuncSetAttribute(gemm_mma, cudaFuncAttributeMaxDynamicSharedMemorySize, DYN_SZ);
    cudaFuncSetAttribute(mi_cluster, cudaFuncAttributeMaxDynamicSharedMemorySize, MI_DYN);

    prep_kernel<<<BB, 512>>>(mq, mr);

    int n4x = (RQ * DD) / 4;
    split2_kernel<<<(n4x + 255) / 256, 256>>>(sq, Xh, Xl, n4x);
    split2_kernel<<<(n4x + 255) / 256, 256>>>(sr, Xh + (size_t)RQ * DD,
                                              Xl + (size_t)RQ * DD, n4x);
    int n4w = (DD * DD) / 4;
    split2_kernel<<<(n4w + 255) / 256, 256>>>(W1, W1h, W1l, n4w);
    split2_kernel<<<(n4w + 255) / 256, 256>>>(W2, W2h, W2l, n4w);

    // layer 1: H = relu(X @ W1^T + b1)
    gemm_mma<<<dim3(2, RTOT / 128), 512, DYN_SZ>>>(
        W1h, W1l, Xh, Xl, b1, Hh, Hl, nullptr, 0);
    // layer 2: P = H @ W2^T + b2 (+ row norms)
    gemm_mma<<<dim3(2, RTOT / 128), 512, DYN_SZ>>>(
        W2h, W2l, Hh, Hl, b2, Ph, Pl, nullptr, 1);
    // cross distances
    gemm_mma<<<dim3(4, 4, BB), 512, DYN_SZ>>>(
        Ph, Pl, Ph, Pl, nullptr, nullptr, nullptr, out_C, 2);

    ebuild_kernel<<<RQ / 8, 256>>>(out_C);

    sinkhorn_cluster<<<BB * 4, 256>>>();

    mi_cluster<<<BB * 8, 256, MI_DYN>>>(out_T, out_C);

    finalize_kernel<<<1, 64>>>(out_sim, out_c);
}

// round 14
// speedup vs baseline: 1.0507x; 1.0507x over previous
#include <cuda_runtime.h>
#include <cuda_fp16.h>
#include <math.h>
#include <stdint.h>

// Problem constants
#define BB 64
#define KK 512
#define MM 512
#define DD 256
#define NI 15
#define MI 3
#define RQ (BB*KK)              // 32768
#define RTOT (2*RQ)             // 65536
#define PLANE ((size_t)KK*MM)
#define TOTE ((size_t)BB*PLANE) // 16777216
#define PSZ ((size_t)RTOT*DD)

// ---------------- device scratch (static; no allocation) ----------------
__device__ __half g_Xh[PSZ], g_Xl[PSZ];
__device__ __half g_Hh[PSZ], g_Hl[PSZ];
__device__ __half g_Ph[PSZ], g_Pl[PSZ];
__device__ __half g_W1h[DD*DD], g_W1l[DD*DD];
__device__ __half g_W2h[DD*DD], g_W2l[DD*DD];
__device__ float g_E[TOTE];
__device__ float g_q2[RQ], g_r2[RQ];
__device__ float g_logmu[RQ], g_lognu[RQ], g_rowRef[RQ];
__device__ float g_la[RQ], g_lb[RQ];
__device__ float g_colsum[3*RQ];
__device__ float g_cvec[BB];

// ---------------- fast exp on FMA pipe ----------------
__device__ __forceinline__ float fexp(float x) {
    x = fminf(fmaxf(x, -87.0f), 88.0f);
    const float L2E    = 1.4426950408889634f;
    const float L2E_LO = 1.9259629911e-8f;
    float t  = fmaf(x, L2E, 12582912.0f);
    float kf = t - 12582912.0f;
    float r  = fmaf(x, L2E, -kf);
    r = fmaf(x, L2E_LO, r);
    float p = 1.5403530e-4f;
    p = fmaf(p, r, 1.33335581e-3f);
    p = fmaf(p, r, 9.61812911e-3f);
    p = fmaf(p, r, 5.55041087e-2f);
    p = fmaf(p, r, 2.40226507e-1f);
    p = fmaf(p, r, 6.93147182e-1f);
    p = fmaf(p, r, 1.0f);
    int ei = (int)kf;
    float s = __int_as_float((ei + 127) << 23);
    return p * s;
}

// ---------------- small PTX helpers ----------------
__device__ __forceinline__ uint32_t smem_u32(const void* p) {
    return (uint32_t)__cvta_generic_to_shared(p);
}
__device__ __forceinline__ void cpasync16(uint32_t s, const void* g) {
    asm volatile("cp.async.cg.shared.global [%0], [%1], 16;" :: "r"(s), "l"(g));
}
#define CP_COMMIT asm volatile("cp.async.commit_group;" ::: "memory")
#define CP_WAIT0  asm volatile("cp.async.wait_group 0;" ::: "memory")
#define CP_WAIT1  asm volatile("cp.async.wait_group 1;" ::: "memory")

__device__ __forceinline__ float dsmem_ld_f(uint32_t saddr, uint32_t rank) {
    uint32_t ra; float v;
    asm volatile("mapa.shared::cluster.u32 %0, %1, %2;" : "=r"(ra) : "r"(saddr), "r"(rank));
    asm volatile("ld.shared::cluster.f32 %0, [%1];" : "=f"(v) : "r"(ra));
    return v;
}
__device__ __forceinline__ void cluster_sync_() {
    asm volatile("barrier.cluster.arrive.aligned;" ::: "memory");
    asm volatile("barrier.cluster.wait.aligned;" ::: "memory");
}

__device__ __forceinline__ void ldsm4(uint32_t& r0, uint32_t& r1, uint32_t& r2,
                                      uint32_t& r3, uint32_t addr) {
    asm volatile("ldmatrix.sync.aligned.m8n8.x4.shared.b16 {%0,%1,%2,%3}, [%4];"
                 : "=r"(r0), "=r"(r1), "=r"(r2), "=r"(r3) : "r"(addr));
}
__device__ __forceinline__ void mma16816h(float* d, const uint32_t* a,
                                          uint32_t b0, uint32_t b1) {
    asm volatile(
        "mma.sync.aligned.m16n8k16.row.col.f32.f16.f16.f32 "
        "{%0,%1,%2,%3}, {%4,%5,%6,%7}, {%8,%9}, {%0,%1,%2,%3};"
        : "+f"(d[0]), "+f"(d[1]), "+f"(d[2]), "+f"(d[3])
        : "r"(a[0]), "r"(a[1]), "r"(a[2]), "r"(a[3]), "r"(b0), "r"(b1));
}

// ---------------- fp32 -> 2x fp16 split ----------------
__global__ void __launch_bounds__(256) split2_kernel(const float* __restrict__ x,
                                                     __half* __restrict__ o1,
                                                     __half* __restrict__ o2,
                                                     int n4) {
    int i = blockIdx.x * 256 + threadIdx.x;
    if (i >= n4) return;
    float4 v = ((const float4*)x)[i];
    float vv[4] = {v.x, v.y, v.z, v.w};
    unsigned short a[4], b[4];
#pragma unroll
    for (int j = 0; j < 4; j++) {
        __half h = __float2half_rn(vv[j]);
        float r1 = vv[j] - __half2float(h);
        __half l = __float2half_rn(r1);
        a[j] = *(unsigned short*)&h; b[j] = *(unsigned short*)&l;
    }
    *(uint2*)&o1[(size_t)i * 4] = *(uint2*)a;
    *(uint2*)&o2[(size_t)i * 4] = *(uint2*)b;
}

// ============================================================================
// fp16x2 tensor-core GEMM (Markidis 3-product). Same as R12 (passing).
// ============================================================================
#define STG_SZ 24576
#define DYN_SZ 67584
__global__ void __launch_bounds__(512) gemm_mma(
    const __half* __restrict__ Ah, const __half* __restrict__ Al,
    const __half* __restrict__ Bh, const __half* __restrict__ Bl,
    const float* __restrict__ bias,
    __half* __restrict__ O1, __half* __restrict__ O2,
    float* __restrict__ Cout, int mode)
{
    extern __shared__ char dynsmem[];
    uint32_t sbase = smem_u32(dynsmem);
    int t = threadIdx.x;
    int wid = t >> 5, lane = t & 31;
    int wm = wid >> 3, wn = wid & 7;

    int arow0, brow0, m0;
    if (mode < 2) {
        arow0 = blockIdx.x * 128; brow0 = blockIdx.y * 128; m0 = arow0;
    } else {
        arow0 = RQ + blockIdx.z * 512 + blockIdx.x * 128;
        brow0 = blockIdx.z * 512 + blockIdx.y * 128;
        m0 = blockIdx.x * 128;
    }

    const __half* srcp[2];
    uint32_t dstoff[2];
#pragma unroll
    for (int j = 0; j < 2; j++) {
        int idx = t + 512 * j;
        int arr = idx >> 8;
        int rem = idx & 255;
        int row = rem >> 1, seg = rem & 1;
        const __half* pl = (arr == 0) ? Ah : (arr == 1) ? Al : (arr == 2) ? Bh : Bl;
        int grow = ((arr < 2) ? arow0 : brow0) + row;
        srcp[j] = pl + (size_t)grow * DD + seg * 8;
        dstoff[j] = (uint32_t)(arr * 6144 + row * 48 + seg * 16);
    }

    float acc[4][2][4];
#pragma unroll
    for (int mt = 0; mt < 4; mt++)
#pragma unroll
        for (int nt = 0; nt < 2; nt++)
#pragma unroll
            for (int v = 0; v < 4; v++) acc[mt][nt][v] = 0.f;

#pragma unroll
    for (int j = 0; j < 2; j++) cpasync16(sbase + dstoff[j], srcp[j]);
    CP_COMMIT;

    uint32_t aAddrBase = (uint32_t)((wm * 64 + (lane & 15)) * 48 + ((lane >> 4) & 1) * 16);
    uint32_t bAddrBase = (uint32_t)(12288 +
        (wn * 16 + (lane & 7) + ((lane >> 4) & 1) * 8) * 48 + ((lane >> 3) & 1) * 16);

#pragma unroll 1
    for (int kc = 0; kc < 16; kc++) {
        if (kc < 15) {
            uint32_t sdst = sbase + ((kc + 1) & 1) * STG_SZ;
#pragma unroll
            for (int j = 0; j < 2; j++)
                cpasync16(sdst + dstoff[j], srcp[j] + (kc + 1) * 16);
            CP_COMMIT;
            CP_WAIT1;
        } else {
            CP_WAIT0;
        }
        __syncthreads();

        uint32_t stg = sbase + (kc & 1) * STG_SZ;
        uint32_t bh[4], bl[4];
        ldsm4(bh[0], bh[1], bh[2], bh[3], stg + bAddrBase);
        ldsm4(bl[0], bl[1], bl[2], bl[3], stg + bAddrBase + 6144);

#pragma unroll
        for (int mt = 0; mt < 4; mt++) {
            uint32_t a_h[4], a_l[4];
            uint32_t aa = stg + aAddrBase + (uint32_t)(mt * 16 * 48);
            ldsm4(a_h[0], a_h[1], a_h[2], a_h[3], aa);
            ldsm4(a_l[0], a_l[1], a_l[2], a_l[3], aa + 6144);
#pragma unroll
            for (int nt = 0; nt < 2; nt++) {
                float* d = acc[mt][nt];
                mma16816h(d, a_h, bh[nt * 2], bh[nt * 2 + 1]);
                mma16816h(d, a_h, bl[nt * 2], bl[nt * 2 + 1]);
                mma16816h(d, a_l, bh[nt * 2], bh[nt * 2 + 1]);
            }
        }
        __syncthreads();
    }

    float* sT = (float*)dynsmem;
#pragma unroll
    for (int mt = 0; mt < 4; mt++)
#pragma unroll
        for (int nt = 0; nt < 2; nt++)
#pragma unroll
            for (int v = 0; v < 4; v++) {
                int n = wn * 16 + nt * 8 + (lane & 3) * 2 + (v & 1);
                int m = wm * 64 + mt * 16 + (lane >> 2) + ((v & 2) ? 8 : 0);
                sT[n * 132 + m] = acc[mt][nt][v];
            }
    __syncthreads();

#pragma unroll 1
    for (int rr = 0; rr < 8; rr++) {
        int n = wid * 8 + rr;
        float4 v4 = *(float4*)&sT[n * 132 + lane * 4];
        float vv[4] = {v4.x, v4.y, v4.z, v4.w};
        int gn = brow0 + n;
        if (mode < 2) {
            float nrm = 0.f;
            unsigned short h[4], lo[4];
#pragma unroll
            for (int j = 0; j < 4; j++) {
                float v = vv[j] + bias[m0 + lane * 4 + j];
                if (mode == 0) v = fmaxf(v, 0.f);
                else nrm += v * v;
                __half hh_ = __float2half_rn(v);
                float r1 = v - __half2float(hh_);
                __half ll_ = __float2half_rn(r1);
                h[j] = *(unsigned short*)&hh_;
                lo[j] = *(unsigned short*)&ll_;
            }
            size_t ob = (size_t)gn * DD + m0 + lane * 4;
            *(uint2*)&O1[ob] = *(uint2*)h;
            *(uint2*)&O2[ob] = *(uint2*)lo;
            if (mode == 1) {
#pragma unroll
                for (int o = 16; o; o >>= 1) nrm += __shfl_xor_sync(~0u, nrm, o);
                if (lane == 0) {
                    if (gn < RQ) atomicAdd(&g_q2[gn], nrm);
                    else         atomicAdd(&g_r2[gn - RQ], nrm);
                }
            }
        } else {
            float q2v = g_q2[gn];
            int rbase = blockIdx.z * 512 + m0 + lane * 4;
            float4 o;
            o.x = sqrtf(fmaxf(q2v + g_r2[rbase + 0] - 2.f * vv[0], 1e-6f));
            o.y = sqrtf(fmaxf(q2v + g_r2[rbase + 1] - 2.f * vv[1], 1e-6f));
            o.z = sqrtf(fmaxf(q2v + g_r2[rbase + 2] - 2.f * vv[2], 1e-6f));
            o.w = sqrtf(fmaxf(q2v + g_r2[rbase + 3] - 2.f * vv[3], 1e-6f));
            *(float4*)&Cout[(size_t)gn * 512 + m0 + lane * 4] = o;
        }
    }
}

// ---------------- prep: logmu/lognu, zero buffers ----------------
__global__ void __launch_bounds__(512) prep_kernel(const float* __restrict__ mq,
                                                   const float* __restrict__ mr) {
    __shared__ float red[512];
    int b = blockIdx.x, t = threadIdx.x;
    float vq = mq[b * 512 + t];
    red[t] = vq; __syncthreads();
    for (int s = 256; s; s >>= 1) { if (t < s) red[t] += red[t + s]; __syncthreads(); }
    float smq = red[0]; __syncthreads();
    g_logmu[b * 512 + t] = logf(fmaxf(vq / (smq + 1e-8f), 1e-8f));

    float vr = mr[b * 512 + t];
    red[t] = vr; __syncthreads();
    for (int s = 256; s; s >>= 1) { if (t < s) red[t] += red[t + s]; __syncthreads(); }
    float smr = red[0]; __syncthreads();
    g_lognu[b * 512 + t] = logf(fmaxf(vr / (smr + 1e-8f), 1e-8f));

    g_q2[b * 512 + t] = 0.f;
    g_r2[b * 512 + t] = 0.f;
    g_colsum[0 * RQ + b * 512 + t] = 0.f;
    g_colsum[1 * RQ + b * 512 + t] = 0.f;
    g_colsum[2 * RQ + b * 512 + t] = 0.f;
    if (t == 0) g_cvec[b] = 0.f;
}

// ============================================================================
// Fused Sinkhorn, single E-sweep per iteration (R12), with ebuild FUSED into
// iteration 0: iter 0 reads C, computes v = -20C + lognu (lognu in smem),
// row max rm inline (same fmaf/max/exp order as the old ebuild => identical E),
// writes E + rowRef, then proceeds with the standard dot/col accumulation.
// ============================================================================
__global__ void __launch_bounds__(256, 1) __cluster_dims__(4, 1, 1)
sinkhorn_cluster(const float* __restrict__ C) {
    __shared__ __align__(16) float s_vb[512];
    __shared__ __align__(16) float s_nu[512];
    __shared__ float s_partial[512];
    __shared__ float s_lb[512];
    __shared__ float s_g[128];
    __shared__ float s_rm[128];
    __shared__ float s_red[256];
    __shared__ float s_locmax;

    int bat = blockIdx.x >> 2;
    int rank = blockIdx.x & 3;
    int t = threadIdx.x;
    int wid = t >> 5, lane = t & 31;
    int rowbase = bat * 512 + rank * 128;
    float* Eb = g_E + (size_t)rowbase * 512;
    const float* Cb = C + (size_t)rowbase * 512;

    s_nu[t]       = g_lognu[bat * 512 + t];
    s_nu[t + 256] = g_lognu[bat * 512 + 256 + t];
    s_lb[t] = 0.f; s_lb[t + 256] = 0.f;
    __syncthreads();

    float sa_prev = 0.f;

    for (int it = 0; it < NI; it++) {
        s_red[t] = fmaxf(s_lb[t], s_lb[t + 256]);
        __syncthreads();
        for (int s = 128; s; s >>= 1) { if (t < s) s_red[t] = fmaxf(s_red[t], s_red[t + s]); __syncthreads(); }
        float sb = s_red[0];
        __syncthreads();
        s_vb[t]       = fexp(s_lb[t] - sb);
        s_vb[t + 256] = fexp(s_lb[t + 256] - sb);
        s_partial[t] = 0.f; s_partial[t + 256] = 0.f;
        __syncthreads();

        float colacc[16];
#pragma unroll
        for (int j = 0; j < 16; j++) colacc[j] = 0.f;
        float gmaxloc = -1e30f;

#pragma unroll 1
        for (int rr = wid; rr < 128; rr += 8) {
            float4 ev[4];
            if (it == 0) {
                // fused ebuild: read C row, build E row (identical math to old ebuild)
                const float4* Cr = (const float4*)(Cb + (size_t)rr * 512);
                float4 vv4[4];
                float rm = -1e30f;
#pragma unroll
                for (int c = 0; c < 4; c++) {
                    float4 cc = Cr[lane + 32 * c];
                    float4 nu = ((const float4*)s_nu)[lane + 32 * c];
                    float4 v;
                    v.x = fmaf(cc.x, -20.f, nu.x);
                    v.y = fmaf(cc.y, -20.f, nu.y);
                    v.z = fmaf(cc.z, -20.f, nu.z);
                    v.w = fmaf(cc.w, -20.f, nu.w);
                    vv4[c] = v;
                    rm = fmaxf(rm, fmaxf(fmaxf(v.x, v.y), fmaxf(v.z, v.w)));
                }
#pragma unroll
                for (int o = 16; o; o >>= 1) rm = fmaxf(rm, __shfl_xor_sync(~0u, rm, o));
                float4* Er = (float4*)(Eb + (size_t)rr * 512);
#pragma unroll
                for (int c = 0; c < 4; c++) {
                    float4 e;
                    e.x = fexp(vv4[c].x - rm); e.y = fexp(vv4[c].y - rm);
                    e.z = fexp(vv4[c].z - rm); e.w = fexp(vv4[c].w - rm);
                    ev[c] = e;
                    Er[lane + 32 * c] = e;
                }
                if (lane == 0) {
                    s_rm[rr] = rm;
                    g_rowRef[rowbase + rr] = rm;
                }
            } else {
                const float4* Er = (const float4*)(Eb + (size_t)rr * 512);
#pragma unroll
                for (int c = 0; c < 4; c++) ev[c] = Er[lane + 32 * c];
            }
            const float4* V = (const float4*)s_vb;
            float acc = 0.f;
#pragma unroll
            for (int c = 0; c < 4; c++) {
                float4 v = V[lane + 32 * c];
                acc += ev[c].x * v.x + ev[c].y * v.y + ev[c].z * v.z + ev[c].w * v.w;
            }
#pragma unroll
            for (int o = 16; o; o >>= 1) acc += __shfl_xor_sync(~0u, acc, o);
            float g = -(sb + logf(fmaxf(acc, 1e-35f)));
            if (lane == 0) s_g[rr] = g;
            gmaxloc = fmaxf(gmaxloc, g);
            float wa = fexp(g - sa_prev);
#pragma unroll
            for (int c = 0; c < 4; c++) {
                colacc[c * 4 + 0] = fmaf(ev[c].x, wa, colacc[c * 4 + 0]);
                colacc[c * 4 + 1] = fmaf(ev[c].y, wa, colacc[c * 4 + 1]);
                colacc[c * 4 + 2] = fmaf(ev[c].z, wa, colacc[c * 4 + 2]);
                colacc[c * 4 + 3] = fmaf(ev[c].w, wa, colacc[c * 4 + 3]);
            }
        }
#pragma unroll
        for (int c = 0; c < 4; c++) {
            int m = (lane + 32 * c) * 4;
            atomicAdd(&s_partial[m + 0], colacc[c * 4 + 0]);
            atomicAdd(&s_partial[m + 1], colacc[c * 4 + 1]);
            atomicAdd(&s_partial[m + 2], colacc[c * 4 + 2]);
            atomicAdd(&s_partial[m + 3], colacc[c * 4 + 3]);
        }
        s_red[t] = gmaxloc;
        __syncthreads();
        for (int s = 128; s; s >>= 1) { if (t < s) s_red[t] = fmaxf(s_red[t], s_red[t + s]); __syncthreads(); }
        if (t == 0) s_locmax = s_red[0];
        __syncthreads();
        cluster_sync_();   // publish partials + locmax

        float sa_new = -1e30f;
        uint32_t lmaddr = smem_u32(&s_locmax);
#pragma unroll
        for (int r = 0; r < 4; r++) sa_new = fmaxf(sa_new, dsmem_ld_f(lmaddr, r));

#pragma unroll
        for (int cg = 0; cg < 2; cg++) {
            int col = t + cg * 256;
            uint32_t pa = smem_u32(&s_partial[col]);
            float s = 0.f;
#pragma unroll
            for (int r = 0; r < 4; r++) s += dsmem_ld_f(pa, r);
            s_lb[col] = -(sa_prev + logf(fmaxf(s, 1e-35f)));
        }
        __syncthreads();
        cluster_sync_();   // remote reads done
        sa_prev = sa_new;
    }

    if (t < 128)
        g_la[rowbase + t] = s_g[t] - (g_logmu[rowbase + t] + s_rm[t]);
    if (rank == 0) {
        g_lb[bat * 512 + t]       = s_lb[t];
        g_lb[bat * 512 + 256 + t] = s_lb[t + 256];
    }
    cluster_sync_();
}

// ---------------- MI it=0 ----------------
__global__ void __launch_bounds__(256) mi_first(float* __restrict__ T) {
    __shared__ float rb[512];
    __shared__ float cs[512];
    int b = blockIdx.x >> 3, r0 = (blockIdx.x & 7) * 64;
    int t = threadIdx.x;
    for (int i = t; i < 512; i += 256) {
        rb[i] = fexp(g_lb[b * 512 + i]);
        cs[i] = 0.f;
    }
    __syncthreads();
    int wid = t >> 5, lane = t & 31;
    float4 csum[4];
#pragma unroll
    for (int c = 0; c < 4; c++) csum[c] = make_float4(0.f, 0.f, 0.f, 0.f);
    for (int rr = wid; rr < 64; rr += 8) {
        int k = r0 + rr;
        size_t base = ((size_t)b * 512 + k) * 512;
        float ra = fexp(g_logmu[b * 512 + k] + g_rowRef[b * 512 + k] + g_la[b * 512 + k]);
        float4 tv[4];
        float rs = 0.f;
#pragma unroll
        for (int c = 0; c < 4; c++) {
            int off = lane + 32 * c;
            float4 e  = ((const float4*)(g_E + base))[off];
            float4 r4 = ((const float4*)rb)[off];
            float4 x;
            x.x = e.x * ra * r4.x; x.y = e.y * ra * r4.y;
            x.z = e.z * ra * r4.z; x.w = e.w * ra * r4.w;
            x.x *= x.x; x.y *= x.y; x.z *= x.z; x.w *= x.w;
            tv[c] = x;
            rs += x.x + x.y + x.z + x.w;
        }
#pragma unroll
        for (int o = 16; o; o >>= 1) rs += __shfl_xor_sync(~0u, rs, o);
        float inv = 1.0f / (rs + 1e-8f);
#pragma unroll
        for (int c = 0; c < 4; c++) {
            int off = lane + 32 * c;
            float4 o4;
            o4.x = tv[c].x * inv; o4.y = tv[c].y * inv;
            o4.z = tv[c].z * inv; o4.w = tv[c].w * inv;
            ((float4*)(T + base))[off] = o4;
            csum[c].x += o4.x; csum[c].y += o4.y;
            csum[c].z += o4.z; csum[c].w += o4.w;
        }
    }
#pragma unroll
    for (int c = 0; c < 4; c++) {
        int m = (lane + 32 * c) * 4;
        atomicAdd(&cs[m + 0], csum[c].x); atomicAdd(&cs[m + 1], csum[c].y);
        atomicAdd(&cs[m + 2], csum[c].z); atomicAdd(&cs[m + 3], csum[c].w);
    }
    __syncthreads();
    for (int i = t; i < 512; i += 256)
        atomicAdd(&g_colsum[b * 512 + i], cs[i]);
}

// ---------------- MI fused ----------------
__global__ void __launch_bounds__(256) mi_fused(float* __restrict__ T, int prev, int it) {
    __shared__ float inv[512];
    __shared__ float cs[512];
    int b = blockIdx.x >> 3, r0 = (blockIdx.x & 7) * 64;
    int t = threadIdx.x;
    for (int i = t; i < 512; i += 256) {
        inv[i] = 1.0f / (g_colsum[(size_t)prev * RQ + b * 512 + i] + 1e-8f);
        cs[i] = 0.f;
    }
    __syncthreads();
    int wid = t >> 5, lane = t & 31;
    float4 csum[4];
#pragma unroll
    for (int c = 0; c < 4; c++) csum[c] = make_float4(0.f, 0.f, 0.f, 0.f);
    for (int rr = wid; rr < 64; rr += 8) {
        int k = r0 + rr;
        size_t base = ((size_t)b * 512 + k) * 512;
        float4 tv[4];
        float rs = 0.f;
#pragma unroll
        for (int c = 0; c < 4; c++) {
            int off = lane + 32 * c;
            float4 x  = ((const float4*)(T + base))[off];
            float4 iv = ((const float4*)inv)[off];
            x.x *= iv.x; x.y *= iv.y; x.z *= iv.z; x.w *= iv.w;
            x.x *= x.x; x.y *= x.y; x.z *= x.z; x.w *= x.w;
            tv[c] = x;
            rs += x.x + x.y + x.z + x.w;
        }
#pragma unroll
        for (int o = 16; o; o >>= 1) rs += __shfl_xor_sync(~0u, rs, o);
        float rinv = 1.0f / (rs + 1e-8f);
#pragma unroll
        for (int c = 0; c < 4; c++) {
            int off = lane + 32 * c;
            float4 o4;
            o4.x = tv[c].x * rinv; o4.y = tv[c].y * rinv;
            o4.z = tv[c].z * rinv; o4.w = tv[c].w * rinv;
            ((float4*)(T + base))[off] = o4;
            csum[c].x += o4.x; csum[c].y += o4.y;
            csum[c].z += o4.z; csum[c].w += o4.w;
        }
    }
#pragma unroll
    for (int c = 0; c < 4; c++) {
        int m = (lane + 32 * c) * 4;
        atomicAdd(&cs[m + 0], csum[c].x); atomicAdd(&cs[m + 1], csum[c].y);
        atomicAdd(&cs[m + 2], csum[c].z); atomicAdd(&cs[m + 3], csum[c].w);
    }
    __syncthreads();
    for (int i = t; i < 512; i += 256)
        atomicAdd(&g_colsum[(size_t)it * RQ + b * 512 + i], cs[i]);
}

// ---------------- MI last ----------------
__global__ void __launch_bounds__(256) mi_last(float* __restrict__ T,
                                               const float* __restrict__ C,
                                               int last) {
    __shared__ float inv[512];
    __shared__ float red[8];
    int b = blockIdx.x >> 3, r0 = (blockIdx.x & 7) * 64;
    int t = threadIdx.x;
    for (int i = t; i < 512; i += 256)
        inv[i] = 1.0f / (g_colsum[(size_t)last * RQ + b * 512 + i] + 1e-8f);
    __syncthreads();
    int wid = t >> 5, lane = t & 31;
    float cacc = 0.f;
    for (int rr = wid; rr < 64; rr += 8) {
        int k = r0 + rr;
        size_t base = ((size_t)b * 512 + k) * 512;
#pragma unroll
        for (int c = 0; c < 4; c++) {
            int off = lane + 32 * c;
            float4 x  = ((const float4*)(T + base))[off];
            float4 iv = ((const float4*)inv)[off];
            x.x *= iv.x; x.y *= iv.y; x.z *= iv.z; x.w *= iv.w;
            ((float4*)(T + base))[off] = x;
            float4 cc = ((const float4*)(C + base))[off];
            cacc += x.x * cc.x + x.y * cc.y + x.z * cc.z + x.w * cc.w;
        }
    }
#pragma unroll
    for (int o = 16; o; o >>= 1) cacc += __shfl_xor_sync(~0u, cacc, o);
    if (lane == 0) red[wid] = cacc;
    __syncthreads();
    if (t == 0) {
        float s = 0.f;
#pragma unroll
        for (int w = 0; w < 8; w++) s += red[w];
        atomicAdd(&g_cvec[b], s);
    }
}

// ---------------- finalize ----------------
__global__ void finalize_kernel(float* __restrict__ sim, float* __restrict__ outc) {
    int b = threadIdx.x;
    if (b < BB) {
        float c = g_cvec[b];
        outc[b] = c;
        sim[b] = 1.0f / (1.0f + expf(c));
    }
}

// ---------------- launch ----------------
extern "C" void kernel_launch(void* const* d_in, const int* in_sizes, int n_in,
                              void* d_out, int out_size) {
    const float* sq = (const float*)d_in[0];
    const float* sr = (const float*)d_in[1];
    const float* mq = (const float*)d_in[2];
    const float* mr = (const float*)d_in[3];
    const float* W1 = (const float*)d_in[4];
    const float* b1 = (const float*)d_in[5];
    const float* W2 = (const float*)d_in[6];
    const float* b2 = (const float*)d_in[7];

    float* out = (float*)d_out;
    float* out_sim = out;
    float* out_T   = out + BB;
    float* out_C   = out + BB + TOTE;
    float* out_c   = out + BB + 2 * TOTE;

    __half *Xh, *Xl, *Hh, *Hl, *Ph, *Pl, *W1h, *W1l, *W2h, *W2l;
    cudaGetSymbolAddress((void**)&Xh, g_Xh);  cudaGetSymbolAddress((void**)&Xl, g_Xl);
    cudaGetSymbolAddress((void**)&Hh, g_Hh);  cudaGetSymbolAddress((void**)&Hl, g_Hl);
    cudaGetSymbolAddress((void**)&Ph, g_Ph);  cudaGetSymbolAddress((void**)&Pl, g_Pl);
    cudaGetSymbolAddress((void**)&W1h, g_W1h); cudaGetSymbolAddress((void**)&W1l, g_W1l);
    cudaGetSymbolAddress((void**)&W2h, g_W2h); cudaGetSymbolAddress((void**)&W2l, g_W2l);

    cudaFuncSetAttribute(gemm_mma, cudaFuncAttributeMaxDynamicSharedMemorySize, DYN_SZ);

    prep_kernel<<<BB, 512>>>(mq, mr);

    int n4x = (RQ * DD) / 4;
    split2_kernel<<<(n4x + 255) / 256, 256>>>(sq, Xh, Xl, n4x);
    split2_kernel<<<(n4x + 255) / 256, 256>>>(sr, Xh + (size_t)RQ * DD,
                                              Xl + (size_t)RQ * DD, n4x);
    int n4w = (DD * DD) / 4;
    split2_kernel<<<(n4w + 255) / 256, 256>>>(W1, W1h, W1l, n4w);
    split2_kernel<<<(n4w + 255) / 256, 256>>>(W2, W2h, W2l, n4w);

    // layer 1: H = relu(X @ W1^T + b1)
    gemm_mma<<<dim3(2, RTOT / 128), 512, DYN_SZ>>>(
        W1h, W1l, Xh, Xl, b1, Hh, Hl, nullptr, 0);
    // layer 2: P = H @ W2^T + b2 (+ row norms)
    gemm_mma<<<dim3(2, RTOT / 128), 512, DYN_SZ>>>(
        W2h, W2l, Hh, Hl, b2, Ph, Pl, nullptr, 1);
    // cross distances
    gemm_mma<<<dim3(4, 4, BB), 512, DYN_SZ>>>(
        Ph, Pl, Ph, Pl, nullptr, nullptr, nullptr, out_C, 2);

    // Sinkhorn with fused ebuild (iter 0 builds E from C)
    sinkhorn_cluster<<<BB * 4, 256>>>(out_C);

    mi_first<<<BB * 8, 256>>>(out_T);
    mi_fused<<<BB * 8, 256>>>(out_T, 0, 1);
    mi_fused<<<BB * 8, 256>>>(out_T, 1, 2);
    mi_last<<<BB * 8, 256>>>(out_T, out_C, 2);

    finalize_kernel<<<1, 64>>>(out_sim, out_c);
}

// round 15
// speedup vs baseline: 1.0746x; 1.0227x over previous
#include <cuda_runtime.h>
#include <cuda_fp16.h>
#include <math.h>
#include <stdint.h>

// Problem constants
#define BB 64
#define KK 512
#define MM 512
#define DD 256
#define NI 15
#define MI 3
#define RQ (BB*KK)              // 32768
#define RTOT (2*RQ)             // 65536
#define PLANE ((size_t)KK*MM)
#define TOTE ((size_t)BB*PLANE) // 16777216
#define PSZ ((size_t)RTOT*DD)

// ---------------- device scratch (static; no allocation) ----------------
__device__ __half g_Xh[PSZ], g_Xl[PSZ];
__device__ __half g_Hh[PSZ], g_Hl[PSZ];
__device__ __half g_Ph[PSZ], g_Pl[PSZ];
__device__ __half g_W1h[DD*DD], g_W1l[DD*DD];
__device__ __half g_W2h[DD*DD], g_W2l[DD*DD];
__device__ float g_E[TOTE];
__device__ float g_q2[RQ], g_r2[RQ];
__device__ float g_logmu[RQ], g_lognu[RQ], g_rowRef[RQ];
__device__ float g_la[RQ], g_lb[RQ];
__device__ float g_colsum[3*RQ];
__device__ float g_cvec[BB];

// ---------------- fast exp on FMA pipe ----------------
__device__ __forceinline__ float fexp(float x) {
    x = fminf(fmaxf(x, -87.0f), 88.0f);
    const float L2E    = 1.4426950408889634f;
    const float L2E_LO = 1.9259629911e-8f;
    float t  = fmaf(x, L2E, 12582912.0f);
    float kf = t - 12582912.0f;
    float r  = fmaf(x, L2E, -kf);
    r = fmaf(x, L2E_LO, r);
    float p = 1.5403530e-4f;
    p = fmaf(p, r, 1.33335581e-3f);
    p = fmaf(p, r, 9.61812911e-3f);
    p = fmaf(p, r, 5.55041087e-2f);
    p = fmaf(p, r, 2.40226507e-1f);
    p = fmaf(p, r, 6.93147182e-1f);
    p = fmaf(p, r, 1.0f);
    int ei = (int)kf;
    float s = __int_as_float((ei + 127) << 23);
    return p * s;
}

// ---------------- small PTX helpers ----------------
__device__ __forceinline__ uint32_t smem_u32(const void* p) {
    return (uint32_t)__cvta_generic_to_shared(p);
}
__device__ __forceinline__ void cpasync16(uint32_t s, const void* g) {
    asm volatile("cp.async.cg.shared.global [%0], [%1], 16;" :: "r"(s), "l"(g));
}
#define CP_COMMIT asm volatile("cp.async.commit_group;" ::: "memory")
#define CP_WAIT0  asm volatile("cp.async.wait_group 0;" ::: "memory")
#define CP_WAIT1  asm volatile("cp.async.wait_group 1;" ::: "memory")

__device__ __forceinline__ float dsmem_ld_f(uint32_t saddr, uint32_t rank) {
    uint32_t ra; float v;
    asm volatile("mapa.shared::cluster.u32 %0, %1, %2;" : "=r"(ra) : "r"(saddr), "r"(rank));
    asm volatile("ld.shared::cluster.f32 %0, [%1];" : "=f"(v) : "r"(ra));
    return v;
}
__device__ __forceinline__ void cluster_sync_() {
    asm volatile("barrier.cluster.arrive.aligned;" ::: "memory");
    asm volatile("barrier.cluster.wait.aligned;" ::: "memory");
}

__device__ __forceinline__ void ldsm4(uint32_t& r0, uint32_t& r1, uint32_t& r2,
                                      uint32_t& r3, uint32_t addr) {
    asm volatile("ldmatrix.sync.aligned.m8n8.x4.shared.b16 {%0,%1,%2,%3}, [%4];"
                 : "=r"(r0), "=r"(r1), "=r"(r2), "=r"(r3) : "r"(addr));
}
__device__ __forceinline__ void mma16816h(float* d, const uint32_t* a,
                                          uint32_t b0, uint32_t b1) {
    asm volatile(
        "mma.sync.aligned.m16n8k16.row.col.f32.f16.f16.f32 "
        "{%0,%1,%2,%3}, {%4,%5,%6,%7}, {%8,%9}, {%0,%1,%2,%3};"
        : "+f"(d[0]), "+f"(d[1]), "+f"(d[2]), "+f"(d[3])
        : "r"(a[0]), "r"(a[1]), "r"(a[2]), "r"(a[3]), "r"(b0), "r"(b1));
}

// ---------------- fp32 -> 2x fp16 split ----------------
__global__ void __launch_bounds__(256) split2_kernel(const float* __restrict__ x,
                                                     __half* __restrict__ o1,
                                                     __half* __restrict__ o2,
                                                     int n4) {
    int i = blockIdx.x * 256 + threadIdx.x;
    if (i >= n4) return;
    float4 v = ((const float4*)x)[i];
    float vv[4] = {v.x, v.y, v.z, v.w};
    unsigned short a[4], b[4];
#pragma unroll
    for (int j = 0; j < 4; j++) {
        __half h = __float2half_rn(vv[j]);
        float r1 = vv[j] - __half2float(h);
        __half l = __float2half_rn(r1);
        a[j] = *(unsigned short*)&h; b[j] = *(unsigned short*)&l;
    }
    *(uint2*)&o1[(size_t)i * 4] = *(uint2*)a;
    *(uint2*)&o2[(size_t)i * 4] = *(uint2*)b;
}

// ============================================================================
// fp16x2 tensor-core GEMM (Markidis 3-product). Same as R12 (passing).
// ============================================================================
#define STG_SZ 24576
#define DYN_SZ 67584
__global__ void __launch_bounds__(512) gemm_mma(
    const __half* __restrict__ Ah, const __half* __restrict__ Al,
    const __half* __restrict__ Bh, const __half* __restrict__ Bl,
    const float* __restrict__ bias,
    __half* __restrict__ O1, __half* __restrict__ O2,
    float* __restrict__ Cout, int mode)
{
    extern __shared__ char dynsmem[];
    uint32_t sbase = smem_u32(dynsmem);
    int t = threadIdx.x;
    int wid = t >> 5, lane = t & 31;
    int wm = wid >> 3, wn = wid & 7;

    int arow0, brow0, m0;
    if (mode < 2) {
        arow0 = blockIdx.x * 128; brow0 = blockIdx.y * 128; m0 = arow0;
    } else {
        arow0 = RQ + blockIdx.z * 512 + blockIdx.x * 128;
        brow0 = blockIdx.z * 512 + blockIdx.y * 128;
        m0 = blockIdx.x * 128;
    }

    const __half* srcp[2];
    uint32_t dstoff[2];
#pragma unroll
    for (int j = 0; j < 2; j++) {
        int idx = t + 512 * j;
        int arr = idx >> 8;
        int rem = idx & 255;
        int row = rem >> 1, seg = rem & 1;
        const __half* pl = (arr == 0) ? Ah : (arr == 1) ? Al : (arr == 2) ? Bh : Bl;
        int grow = ((arr < 2) ? arow0 : brow0) + row;
        srcp[j] = pl + (size_t)grow * DD + seg * 8;
        dstoff[j] = (uint32_t)(arr * 6144 + row * 48 + seg * 16);
    }

    float acc[4][2][4];
#pragma unroll
    for (int mt = 0; mt < 4; mt++)
#pragma unroll
        for (int nt = 0; nt < 2; nt++)
#pragma unroll
            for (int v = 0; v < 4; v++) acc[mt][nt][v] = 0.f;

#pragma unroll
    for (int j = 0; j < 2; j++) cpasync16(sbase + dstoff[j], srcp[j]);
    CP_COMMIT;

    uint32_t aAddrBase = (uint32_t)((wm * 64 + (lane & 15)) * 48 + ((lane >> 4) & 1) * 16);
    uint32_t bAddrBase = (uint32_t)(12288 +
        (wn * 16 + (lane & 7) + ((lane >> 4) & 1) * 8) * 48 + ((lane >> 3) & 1) * 16);

#pragma unroll 1
    for (int kc = 0; kc < 16; kc++) {
        if (kc < 15) {
            uint32_t sdst = sbase + ((kc + 1) & 1) * STG_SZ;
#pragma unroll
            for (int j = 0; j < 2; j++)
                cpasync16(sdst + dstoff[j], srcp[j] + (kc + 1) * 16);
            CP_COMMIT;
            CP_WAIT1;
        } else {
            CP_WAIT0;
        }
        __syncthreads();

        uint32_t stg = sbase + (kc & 1) * STG_SZ;
        uint32_t bh[4], bl[4];
        ldsm4(bh[0], bh[1], bh[2], bh[3], stg + bAddrBase);
        ldsm4(bl[0], bl[1], bl[2], bl[3], stg + bAddrBase + 6144);

#pragma unroll
        for (int mt = 0; mt < 4; mt++) {
            uint32_t a_h[4], a_l[4];
            uint32_t aa = stg + aAddrBase + (uint32_t)(mt * 16 * 48);
            ldsm4(a_h[0], a_h[1], a_h[2], a_h[3], aa);
            ldsm4(a_l[0], a_l[1], a_l[2], a_l[3], aa + 6144);
#pragma unroll
            for (int nt = 0; nt < 2; nt++) {
                float* d = acc[mt][nt];
                mma16816h(d, a_h, bh[nt * 2], bh[nt * 2 + 1]);
                mma16816h(d, a_h, bl[nt * 2], bl[nt * 2 + 1]);
                mma16816h(d, a_l, bh[nt * 2], bh[nt * 2 + 1]);
            }
        }
        __syncthreads();
    }

    float* sT = (float*)dynsmem;
#pragma unroll
    for (int mt = 0; mt < 4; mt++)
#pragma unroll
        for (int nt = 0; nt < 2; nt++)
#pragma unroll
            for (int v = 0; v < 4; v++) {
                int n = wn * 16 + nt * 8 + (lane & 3) * 2 + (v & 1);
                int m = wm * 64 + mt * 16 + (lane >> 2) + ((v & 2) ? 8 : 0);
                sT[n * 132 + m] = acc[mt][nt][v];
            }
    __syncthreads();

#pragma unroll 1
    for (int rr = 0; rr < 8; rr++) {
        int n = wid * 8 + rr;
        float4 v4 = *(float4*)&sT[n * 132 + lane * 4];
        float vv[4] = {v4.x, v4.y, v4.z, v4.w};
        int gn = brow0 + n;
        if (mode < 2) {
            float nrm = 0.f;
            unsigned short h[4], lo[4];
#pragma unroll
            for (int j = 0; j < 4; j++) {
                float v = vv[j] + bias[m0 + lane * 4 + j];
                if (mode == 0) v = fmaxf(v, 0.f);
                else nrm += v * v;
                __half hh_ = __float2half_rn(v);
                float r1 = v - __half2float(hh_);
                __half ll_ = __float2half_rn(r1);
                h[j] = *(unsigned short*)&hh_;
                lo[j] = *(unsigned short*)&ll_;
            }
            size_t ob = (size_t)gn * DD + m0 + lane * 4;
            *(uint2*)&O1[ob] = *(uint2*)h;
            *(uint2*)&O2[ob] = *(uint2*)lo;
            if (mode == 1) {
#pragma unroll
                for (int o = 16; o; o >>= 1) nrm += __shfl_xor_sync(~0u, nrm, o);
                if (lane == 0) {
                    if (gn < RQ) atomicAdd(&g_q2[gn], nrm);
                    else         atomicAdd(&g_r2[gn - RQ], nrm);
                }
            }
        } else {
            float q2v = g_q2[gn];
            int rbase = blockIdx.z * 512 + m0 + lane * 4;
            float4 o;
            o.x = sqrtf(fmaxf(q2v + g_r2[rbase + 0] - 2.f * vv[0], 1e-6f));
            o.y = sqrtf(fmaxf(q2v + g_r2[rbase + 1] - 2.f * vv[1], 1e-6f));
            o.z = sqrtf(fmaxf(q2v + g_r2[rbase + 2] - 2.f * vv[2], 1e-6f));
            o.w = sqrtf(fmaxf(q2v + g_r2[rbase + 3] - 2.f * vv[3], 1e-6f));
            *(float4*)&Cout[(size_t)gn * 512 + m0 + lane * 4] = o;
        }
    }
}

// ---------------- prep: logmu/lognu, zero buffers ----------------
__global__ void __launch_bounds__(512) prep_kernel(const float* __restrict__ mq,
                                                   const float* __restrict__ mr) {
    __shared__ float red[512];
    int b = blockIdx.x, t = threadIdx.x;
    float vq = mq[b * 512 + t];
    red[t] = vq; __syncthreads();
    for (int s = 256; s; s >>= 1) { if (t < s) red[t] += red[t + s]; __syncthreads(); }
    float smq = red[0]; __syncthreads();
    g_logmu[b * 512 + t] = logf(fmaxf(vq / (smq + 1e-8f), 1e-8f));

    float vr = mr[b * 512 + t];
    red[t] = vr; __syncthreads();
    for (int s = 256; s; s >>= 1) { if (t < s) red[t] += red[t + s]; __syncthreads(); }
    float smr = red[0]; __syncthreads();
    g_lognu[b * 512 + t] = logf(fmaxf(vr / (smr + 1e-8f), 1e-8f));

    g_q2[b * 512 + t] = 0.f;
    g_r2[b * 512 + t] = 0.f;
    g_colsum[0 * RQ + b * 512 + t] = 0.f;
    g_colsum[1 * RQ + b * 512 + t] = 0.f;
    g_colsum[2 * RQ + b * 512 + t] = 0.f;
    if (t == 0) g_cvec[b] = 0.f;
}

// ============================================================================
// Fused Sinkhorn (single E-sweep, R12) with ebuild PEELED into a pre-loop
// iteration-0 sweep: lb=0 => sb=0, vb=1, so iter 0 reads C, builds E rows
// (identical fmaf/max/exp order to the old ebuild => identical bits), writes
// E + rowRef, computes g = -log(rowsum(E)) and col partials with wa=exp(g)
// (sa_prev = 0, exact-safe). Main loop it=1..14 is the unmodified R12 body.
// ============================================================================
__global__ void __launch_bounds__(256, 1) __cluster_dims__(4, 1, 1)
sinkhorn_cluster(const float* __restrict__ C) {
    __shared__ __align__(16) float s_vb[512];
    __shared__ __align__(16) float s_nu[512];
    __shared__ float s_partial[512];
    __shared__ float s_lb[512];
    __shared__ float s_g[128];
    __shared__ float s_rm[128];
    __shared__ float s_red[256];
    __shared__ float s_locmax;

    int bat = blockIdx.x >> 2;
    int rank = blockIdx.x & 3;
    int t = threadIdx.x;
    int wid = t >> 5, lane = t & 31;
    int rowbase = bat * 512 + rank * 128;
    float* Eb = g_E + (size_t)rowbase * 512;
    const float* Cb = C + (size_t)rowbase * 512;

    s_nu[t]       = g_lognu[bat * 512 + t];
    s_nu[t + 256] = g_lognu[bat * 512 + 256 + t];
    s_partial[t] = 0.f; s_partial[t + 256] = 0.f;
    __syncthreads();

    // ======== peeled iteration 0 (fused ebuild; sb=0, vb=1, sa_prev=0) ======
    {
        float colacc[16];
#pragma unroll
        for (int j = 0; j < 16; j++) colacc[j] = 0.f;
        float gmaxloc = -1e30f;

#pragma unroll 1
        for (int rr = wid; rr < 128; rr += 8) {
            const float4* Cr = (const float4*)(Cb + (size_t)rr * 512);
            float4 ev[4];
            float rm = -1e30f;
#pragma unroll
            for (int c = 0; c < 4; c++) {
                float4 cc = Cr[lane + 32 * c];
                float4 nu = ((const float4*)s_nu)[lane + 32 * c];
                float4 v;
                v.x = fmaf(cc.x, -20.f, nu.x);
                v.y = fmaf(cc.y, -20.f, nu.y);
                v.z = fmaf(cc.z, -20.f, nu.z);
                v.w = fmaf(cc.w, -20.f, nu.w);
                ev[c] = v;
                rm = fmaxf(rm, fmaxf(fmaxf(v.x, v.y), fmaxf(v.z, v.w)));
            }
#pragma unroll
            for (int o = 16; o; o >>= 1) rm = fmaxf(rm, __shfl_xor_sync(~0u, rm, o));
            float4* Er = (float4*)(Eb + (size_t)rr * 512);
            float acc = 0.f;
#pragma unroll
            for (int c = 0; c < 4; c++) {
                float4 e;
                e.x = fexp(ev[c].x - rm); e.y = fexp(ev[c].y - rm);
                e.z = fexp(ev[c].z - rm); e.w = fexp(ev[c].w - rm);
                ev[c] = e;
                Er[lane + 32 * c] = e;
                acc += e.x + e.y + e.z + e.w;
            }
#pragma unroll
            for (int o = 16; o; o >>= 1) acc += __shfl_xor_sync(~0u, acc, o);
            float g = -logf(fmaxf(acc, 1e-35f));
            if (lane == 0) {
                s_g[rr] = g;
                s_rm[rr] = rm;
                g_rowRef[rowbase + rr] = rm;
            }
            gmaxloc = fmaxf(gmaxloc, g);
            float wa = fexp(g);
#pragma unroll
            for (int c = 0; c < 4; c++) {
                colacc[c * 4 + 0] = fmaf(ev[c].x, wa, colacc[c * 4 + 0]);
                colacc[c * 4 + 1] = fmaf(ev[c].y, wa, colacc[c * 4 + 1]);
                colacc[c * 4 + 2] = fmaf(ev[c].z, wa, colacc[c * 4 + 2]);
                colacc[c * 4 + 3] = fmaf(ev[c].w, wa, colacc[c * 4 + 3]);
            }
        }
#pragma unroll
        for (int c = 0; c < 4; c++) {
            int m = (lane + 32 * c) * 4;
            atomicAdd(&s_partial[m + 0], colacc[c * 4 + 0]);
            atomicAdd(&s_partial[m + 1], colacc[c * 4 + 1]);
            atomicAdd(&s_partial[m + 2], colacc[c * 4 + 2]);
            atomicAdd(&s_partial[m + 3], colacc[c * 4 + 3]);
        }
        s_red[t] = gmaxloc;
        __syncthreads();
        for (int s = 128; s; s >>= 1) { if (t < s) s_red[t] = fmaxf(s_red[t], s_red[t + s]); __syncthreads(); }
        if (t == 0) s_locmax = s_red[0];
        __syncthreads();
        cluster_sync_();   // publish partials + locmax
    }

    float sa_prev = -1e30f;
    {
        uint32_t lmaddr = smem_u32(&s_locmax);
#pragma unroll
        for (int r = 0; r < 4; r++) sa_prev = fmaxf(sa_prev, dsmem_ld_f(lmaddr, r));
#pragma unroll
        for (int cg = 0; cg < 2; cg++) {
            int col = t + cg * 256;
            uint32_t pa = smem_u32(&s_partial[col]);
            float s = 0.f;
#pragma unroll
            for (int r = 0; r < 4; r++) s += dsmem_ld_f(pa, r);
            s_lb[col] = -(0.f + logf(fmaxf(s, 1e-35f)));
        }
        __syncthreads();
        cluster_sync_();   // remote reads done
    }

    // ======== main loop it = 1..14 (unmodified R12 body) ====================
    for (int it = 1; it < NI; it++) {
        s_red[t] = fmaxf(s_lb[t], s_lb[t + 256]);
        __syncthreads();
        for (int s = 128; s; s >>= 1) { if (t < s) s_red[t] = fmaxf(s_red[t], s_red[t + s]); __syncthreads(); }
        float sb = s_red[0];
        __syncthreads();
        s_vb[t]       = fexp(s_lb[t] - sb);
        s_vb[t + 256] = fexp(s_lb[t + 256] - sb);
        s_partial[t] = 0.f; s_partial[t + 256] = 0.f;
        __syncthreads();

        float colacc[16];
#pragma unroll
        for (int j = 0; j < 16; j++) colacc[j] = 0.f;
        float gmaxloc = -1e30f;

#pragma unroll 1
        for (int rr = wid; rr < 128; rr += 8) {
            const float4* Er = (const float4*)(Eb + (size_t)rr * 512);
            const float4* V  = (const float4*)s_vb;
            float4 ev[4];
            float acc = 0.f;
#pragma unroll
            for (int c = 0; c < 4; c++) {
                ev[c] = Er[lane + 32 * c];
                float4 v = V[lane + 32 * c];
                acc += ev[c].x * v.x + ev[c].y * v.y + ev[c].z * v.z + ev[c].w * v.w;
            }
#pragma unroll
            for (int o = 16; o; o >>= 1) acc += __shfl_xor_sync(~0u, acc, o);
            float g = -(sb + logf(fmaxf(acc, 1e-35f)));
            if (lane == 0) s_g[rr] = g;
            gmaxloc = fmaxf(gmaxloc, g);
            float wa = fexp(g - sa_prev);
#pragma unroll
            for (int c = 0; c < 4; c++) {
                colacc[c * 4 + 0] = fmaf(ev[c].x, wa, colacc[c * 4 + 0]);
                colacc[c * 4 + 1] = fmaf(ev[c].y, wa, colacc[c * 4 + 1]);
                colacc[c * 4 + 2] = fmaf(ev[c].z, wa, colacc[c * 4 + 2]);
                colacc[c * 4 + 3] = fmaf(ev[c].w, wa, colacc[c * 4 + 3]);
            }
        }
#pragma unroll
        for (int c = 0; c < 4; c++) {
            int m = (lane + 32 * c) * 4;
            atomicAdd(&s_partial[m + 0], colacc[c * 4 + 0]);
            atomicAdd(&s_partial[m + 1], colacc[c * 4 + 1]);
            atomicAdd(&s_partial[m + 2], colacc[c * 4 + 2]);
            atomicAdd(&s_partial[m + 3], colacc[c * 4 + 3]);
        }
        s_red[t] = gmaxloc;
        __syncthreads();
        for (int s = 128; s; s >>= 1) { if (t < s) s_red[t] = fmaxf(s_red[t], s_red[t + s]); __syncthreads(); }
        if (t == 0) s_locmax = s_red[0];
        __syncthreads();
        cluster_sync_();   // publish partials + locmax

        float sa_new = -1e30f;
        uint32_t lmaddr = smem_u32(&s_locmax);
#pragma unroll
        for (int r = 0; r < 4; r++) sa_new = fmaxf(sa_new, dsmem_ld_f(lmaddr, r));

#pragma unroll
        for (int cg = 0; cg < 2; cg++) {
            int col = t + cg * 256;
            uint32_t pa = smem_u32(&s_partial[col]);
            float s = 0.f;
#pragma unroll
            for (int r = 0; r < 4; r++) s += dsmem_ld_f(pa, r);
            s_lb[col] = -(sa_prev + logf(fmaxf(s, 1e-35f)));
        }
        __syncthreads();
        cluster_sync_();   // remote reads done
        sa_prev = sa_new;
    }

    if (t < 128)
        g_la[rowbase + t] = s_g[t] - (g_logmu[rowbase + t] + s_rm[t]);
    if (rank == 0) {
        g_lb[bat * 512 + t]       = s_lb[t];
        g_lb[bat * 512 + 256 + t] = s_lb[t + 256];
    }
    cluster_sync_();
}

// ---------------- MI it=0 ----------------
__global__ void __launch_bounds__(256) mi_first(float* __restrict__ T) {
    __shared__ float rb[512];
    __shared__ float cs[512];
    int b = blockIdx.x >> 3, r0 = (blockIdx.x & 7) * 64;
    int t = threadIdx.x;
    for (int i = t; i < 512; i += 256) {
        rb[i] = fexp(g_lb[b * 512 + i]);
        cs[i] = 0.f;
    }
    __syncthreads();
    int wid = t >> 5, lane = t & 31;
    float4 csum[4];
#pragma unroll
    for (int c = 0; c < 4; c++) csum[c] = make_float4(0.f, 0.f, 0.f, 0.f);
    for (int rr = wid; rr < 64; rr += 8) {
        int k = r0 + rr;
        size_t base = ((size_t)b * 512 + k) * 512;
        float ra = fexp(g_logmu[b * 512 + k] + g_rowRef[b * 512 + k] + g_la[b * 512 + k]);
        float4 tv[4];
        float rs = 0.f;
#pragma unroll
        for (int c = 0; c < 4; c++) {
            int off = lane + 32 * c;
            float4 e  = ((const float4*)(g_E + base))[off];
            float4 r4 = ((const float4*)rb)[off];
            float4 x;
            x.x = e.x * ra * r4.x; x.y = e.y * ra * r4.y;
            x.z = e.z * ra * r4.z; x.w = e.w * ra * r4.w;
            x.x *= x.x; x.y *= x.y; x.z *= x.z; x.w *= x.w;
            tv[c] = x;
            rs += x.x + x.y + x.z + x.w;
        }
#pragma unroll
        for (int o = 16; o; o >>= 1) rs += __shfl_xor_sync(~0u, rs, o);
        float inv = 1.0f / (rs + 1e-8f);
#pragma unroll
        for (int c = 0; c < 4; c++) {
            int off = lane + 32 * c;
            float4 o4;
            o4.x = tv[c].x * inv; o4.y = tv[c].y * inv;
            o4.z = tv[c].z * inv; o4.w = tv[c].w * inv;
            ((float4*)(T + base))[off] = o4;
            csum[c].x += o4.x; csum[c].y += o4.y;
            csum[c].z += o4.z; csum[c].w += o4.w;
        }
    }
#pragma unroll
    for (int c = 0; c < 4; c++) {
        int m = (lane + 32 * c) * 4;
        atomicAdd(&cs[m + 0], csum[c].x); atomicAdd(&cs[m + 1], csum[c].y);
        atomicAdd(&cs[m + 2], csum[c].z); atomicAdd(&cs[m + 3], csum[c].w);
    }
    __syncthreads();
    for (int i = t; i < 512; i += 256)
        atomicAdd(&g_colsum[b * 512 + i], cs[i]);
}

// ---------------- MI fused ----------------
__global__ void __launch_bounds__(256) mi_fused(float* __restrict__ T, int prev, int it) {
    __shared__ float inv[512];
    __shared__ float cs[512];
    int b = blockIdx.x >> 3, r0 = (blockIdx.x & 7) * 64;
    int t = threadIdx.x;
    for (int i = t; i < 512; i += 256) {
        inv[i] = 1.0f / (g_colsum[(size_t)prev * RQ + b * 512 + i] + 1e-8f);
        cs[i] = 0.f;
    }
    __syncthreads();
    int wid = t >> 5, lane = t & 31;
    float4 csum[4];
#pragma unroll
    for (int c = 0; c < 4; c++) csum[c] = make_float4(0.f, 0.f, 0.f, 0.f);
    for (int rr = wid; rr < 64; rr += 8) {
        int k = r0 + rr;
        size_t base = ((size_t)b * 512 + k) * 512;
        float4 tv[4];
        float rs = 0.f;
#pragma unroll
        for (int c = 0; c < 4; c++) {
            int off = lane + 32 * c;
            float4 x  = ((const float4*)(T + base))[off];
            float4 iv = ((const float4*)inv)[off];
            x.x *= iv.x; x.y *= iv.y; x.z *= iv.z; x.w *= iv.w;
            x.x *= x.x; x.y *= x.y; x.z *= x.z; x.w *= x.w;
            tv[c] = x;
            rs += x.x + x.y + x.z + x.w;
        }
#pragma unroll
        for (int o = 16; o; o >>= 1) rs += __shfl_xor_sync(~0u, rs, o);
        float rinv = 1.0f / (rs + 1e-8f);
#pragma unroll
        for (int c = 0; c < 4; c++) {
            int off = lane + 32 * c;
            float4 o4;
            o4.x = tv[c].x * rinv; o4.y = tv[c].y * rinv;
            o4.z = tv[c].z * rinv; o4.w = tv[c].w * rinv;
            ((float4*)(T + base))[off] = o4;
            csum[c].x += o4.x; csum[c].y += o4.y;
            csum[c].z += o4.z; csum[c].w += o4.w;
        }
    }
#pragma unroll
    for (int c = 0; c < 4; c++) {
        int m = (lane + 32 * c) * 4;
        atomicAdd(&cs[m + 0], csum[c].x); atomicAdd(&cs[m + 1], csum[c].y);
        atomicAdd(&cs[m + 2], csum[c].z); atomicAdd(&cs[m + 3], csum[c].w);
    }
    __syncthreads();
    for (int i = t; i < 512; i += 256)
        atomicAdd(&g_colsum[(size_t)it * RQ + b * 512 + i], cs[i]);
}

// ---------------- MI last ----------------
__global__ void __launch_bounds__(256) mi_last(float* __restrict__ T,
                                               const float* __restrict__ C,
                                               int last) {
    __shared__ float inv[512];
    __shared__ float red[8];
    int b = blockIdx.x >> 3, r0 = (blockIdx.x & 7) * 64;
    int t = threadIdx.x;
    for (int i = t; i < 512; i += 256)
        inv[i] = 1.0f / (g_colsum[(size_t)last * RQ + b * 512 + i] + 1e-8f);
    __syncthreads();
    int wid = t >> 5, lane = t & 31;
    float cacc = 0.f;
    for (int rr = wid; rr < 64; rr += 8) {
        int k = r0 + rr;
        size_t base = ((size_t)b * 512 + k) * 512;
#pragma unroll
        for (int c = 0; c < 4; c++) {
            int off = lane + 32 * c;
            float4 x  = ((const float4*)(T + base))[off];
            float4 iv = ((const float4*)inv)[off];
            x.x *= iv.x; x.y *= iv.y; x.z *= iv.z; x.w *= iv.w;
            ((float4*)(T + base))[off] = x;
            float4 cc = ((const float4*)(C + base))[off];
            cacc += x.x * cc.x + x.y * cc.y + x.z * cc.z + x.w * cc.w;
        }
    }
#pragma unroll
    for (int o = 16; o; o >>= 1) cacc += __shfl_xor_sync(~0u, cacc, o);
    if (lane == 0) red[wid] = cacc;
    __syncthreads();
    if (t == 0) {
        float s = 0.f;
#pragma unroll
        for (int w = 0; w < 8; w++) s += red[w];
        atomicAdd(&g_cvec[b], s);
    }
}

// ---------------- finalize ----------------
__global__ void finalize_kernel(float* __restrict__ sim, float* __restrict__ outc) {
    int b = threadIdx.x;
    if (b < BB) {
        float c = g_cvec[b];
        outc[b] = c;
        sim[b] = 1.0f / (1.0f + expf(c));
    }
}

// ---------------- launch ----------------
extern "C" void kernel_launch(void* const* d_in, const int* in_sizes, int n_in,
                              void* d_out, int out_size) {
    const float* sq = (const float*)d_in[0];
    const float* sr = (const float*)d_in[1];
    const float* mq = (const float*)d_in[2];
    const float* mr = (const float*)d_in[3];
    const float* W1 = (const float*)d_in[4];
    const float* b1 = (const float*)d_in[5];
    const float* W2 = (const float*)d_in[6];
    const float* b2 = (const float*)d_in[7];

    float* out = (float*)d_out;
    float* out_sim = out;
    float* out_T   = out + BB;
    float* out_C   = out + BB + TOTE;
    float* out_c   = out + BB + 2 * TOTE;

    __half *Xh, *Xl, *Hh, *Hl, *Ph, *Pl, *W1h, *W1l, *W2h, *W2l;
    cudaGetSymbolAddress((void**)&Xh, g_Xh);  cudaGetSymbolAddress((void**)&Xl, g_Xl);
    cudaGetSymbolAddress((void**)&Hh, g_Hh);  cudaGetSymbolAddress((void**)&Hl, g_Hl);
    cudaGetSymbolAddress((void**)&Ph, g_Ph);  cudaGetSymbolAddress((void**)&Pl, g_Pl);
    cudaGetSymbolAddress((void**)&W1h, g_W1h); cudaGetSymbolAddress((void**)&W1l, g_W1l);
    cudaGetSymbolAddress((void**)&W2h, g_W2h); cudaGetSymbolAddress((void**)&W2l, g_W2l);

    cudaFuncSetAttribute(gemm_mma, cudaFuncAttributeMaxDynamicSharedMemorySize, DYN_SZ);

    prep_kernel<<<BB, 512>>>(mq, mr);

    int n4x = (RQ * DD) / 4;
    split2_kernel<<<(n4x + 255) / 256, 256>>>(sq, Xh, Xl, n4x);
    split2_kernel<<<(n4x + 255) / 256, 256>>>(sr, Xh + (size_t)RQ * DD,
                                              Xl + (size_t)RQ * DD, n4x);
    int n4w = (DD * DD) / 4;
    split2_kernel<<<(n4w + 255) / 256, 256>>>(W1, W1h, W1l, n4w);
    split2_kernel<<<(n4w + 255) / 256, 256>>>(W2, W2h, W2l, n4w);

    // layer 1: H = relu(X @ W1^T + b1)
    gemm_mma<<<dim3(2, RTOT / 128), 512, DYN_SZ>>>(
        W1h, W1l, Xh, Xl, b1, Hh, Hl, nullptr, 0);
    // layer 2: P = H @ W2^T + b2 (+ row norms)
    gemm_mma<<<dim3(2, RTOT / 128), 512, DYN_SZ>>>(
        W2h, W2l, Hh, Hl, b2, Ph, Pl, nullptr, 1);
    // cross distances
    gemm_mma<<<dim3(4, 4, BB), 512, DYN_SZ>>>(
        Ph, Pl, Ph, Pl, nullptr, nullptr, nullptr, out_C, 2);

    // Sinkhorn with peeled fused ebuild (iter 0 builds E from C)
    sinkhorn_cluster<<<BB * 4, 256>>>(out_C);

    mi_first<<<BB * 8, 256>>>(out_T);
    mi_fused<<<BB * 8, 256>>>(out_T, 0, 1);
    mi_fused<<<BB * 8, 256>>>(out_T, 1, 2);
    mi_last<<<BB * 8, 256>>>(out_T, out_C, 2);

    finalize_kernel<<<1, 64>>>(out_sim, out_c);
}

// round 16
// speedup vs baseline: 1.0814x; 1.0063x over previous
#include <cuda_runtime.h>
#include <cuda_fp16.h>
#include <math.h>
#include <stdint.h>

// Problem constants
#define BB 64
#define KK 512
#define MM 512
#define DD 256
#define NI 15
#define MI 3
#define RQ (BB*KK)              // 32768
#define RTOT (2*RQ)             // 65536
#define PLANE ((size_t)KK*MM)
#define TOTE ((size_t)BB*PLANE) // 16777216
#define PSZ ((size_t)RTOT*DD)

// ---------------- device scratch (static; no allocation) ----------------
__device__ __half g_Xh[PSZ], g_Xl[PSZ];
__device__ __half g_Hh[PSZ], g_Hl[PSZ];
__device__ __half g_Ph[PSZ], g_Pl[PSZ];
__device__ __half g_W1h[DD*DD], g_W1l[DD*DD];
__device__ __half g_W2h[DD*DD], g_W2l[DD*DD];
__device__ float g_E[TOTE];
__device__ float g_q2[RQ], g_r2[RQ];
__device__ float g_logmu[RQ], g_lognu[RQ], g_rowRef[RQ];
__device__ float g_la[RQ], g_lb[RQ];
__device__ float g_cvec[BB];

// ---------------- fast exp on FMA pipe ----------------
__device__ __forceinline__ float fexp(float x) {
    x = fminf(fmaxf(x, -87.0f), 88.0f);
    const float L2E    = 1.4426950408889634f;
    const float L2E_LO = 1.9259629911e-8f;
    float t  = fmaf(x, L2E, 12582912.0f);
    float kf = t - 12582912.0f;
    float r  = fmaf(x, L2E, -kf);
    r = fmaf(x, L2E_LO, r);
    float p = 1.5403530e-4f;
    p = fmaf(p, r, 1.33335581e-3f);
    p = fmaf(p, r, 9.61812911e-3f);
    p = fmaf(p, r, 5.55041087e-2f);
    p = fmaf(p, r, 2.40226507e-1f);
    p = fmaf(p, r, 6.93147182e-1f);
    p = fmaf(p, r, 1.0f);
    int ei = (int)kf;
    float s = __int_as_float((ei + 127) << 23);
    return p * s;
}

// ---------------- small PTX helpers ----------------
__device__ __forceinline__ uint32_t smem_u32(const void* p) {
    return (uint32_t)__cvta_generic_to_shared(p);
}
__device__ __forceinline__ void cpasync16(uint32_t s, const void* g) {
    asm volatile("cp.async.cg.shared.global [%0], [%1], 16;" :: "r"(s), "l"(g));
}
#define CP_COMMIT asm volatile("cp.async.commit_group;" ::: "memory")
#define CP_WAIT0  asm volatile("cp.async.wait_group 0;" ::: "memory")
#define CP_WAIT1  asm volatile("cp.async.wait_group 1;" ::: "memory")

__device__ __forceinline__ float dsmem_ld_f(uint32_t saddr, uint32_t rank) {
    uint32_t ra; float v;
    asm volatile("mapa.shared::cluster.u32 %0, %1, %2;" : "=r"(ra) : "r"(saddr), "r"(rank));
    asm volatile("ld.shared::cluster.f32 %0, [%1];" : "=f"(v) : "r"(ra));
    return v;
}
__device__ __forceinline__ void cluster_sync_() {
    asm volatile("barrier.cluster.arrive.aligned;" ::: "memory");
    asm volatile("barrier.cluster.wait.aligned;" ::: "memory");
}

__device__ __forceinline__ void ldsm4(uint32_t& r0, uint32_t& r1, uint32_t& r2,
                                      uint32_t& r3, uint32_t addr) {
    asm volatile("ldmatrix.sync.aligned.m8n8.x4.shared.b16 {%0,%1,%2,%3}, [%4];"
                 : "=r"(r0), "=r"(r1), "=r"(r2), "=r"(r3) : "r"(addr));
}
__device__ __forceinline__ void mma16816h(float* d, const uint32_t* a,
                                          uint32_t b0, uint32_t b1) {
    asm volatile(
        "mma.sync.aligned.m16n8k16.row.col.f32.f16.f16.f32 "
        "{%0,%1,%2,%3}, {%4,%5,%6,%7}, {%8,%9}, {%0,%1,%2,%3};"
        : "+f"(d[0]), "+f"(d[1]), "+f"(d[2]), "+f"(d[3])
        : "r"(a[0]), "r"(a[1]), "r"(a[2]), "r"(a[3]), "r"(b0), "r"(b1));
}

// ---------------- fp32 -> 2x fp16 split ----------------
__global__ void __launch_bounds__(256) split2_kernel(const float* __restrict__ x,
                                                     __half* __restrict__ o1,
                                                     __half* __restrict__ o2,
                                                     int n4) {
    int i = blockIdx.x * 256 + threadIdx.x;
    if (i >= n4) return;
    float4 v = ((const float4*)x)[i];
    float vv[4] = {v.x, v.y, v.z, v.w};
    unsigned short a[4], b[4];
#pragma unroll
    for (int j = 0; j < 4; j++) {
        __half h = __float2half_rn(vv[j]);
        float r1 = vv[j] - __half2float(h);
        __half l = __float2half_rn(r1);
        a[j] = *(unsigned short*)&h; b[j] = *(unsigned short*)&l;
    }
    *(uint2*)&o1[(size_t)i * 4] = *(uint2*)a;
    *(uint2*)&o2[(size_t)i * 4] = *(uint2*)b;
}

// ============================================================================
// fp16x2 tensor-core GEMM (Markidis 3-product). Same as R12 (passing).
// ============================================================================
#define STG_SZ 24576
#define DYN_SZ 67584
__global__ void __launch_bounds__(512) gemm_mma(
    const __half* __restrict__ Ah, const __half* __restrict__ Al,
    const __half* __restrict__ Bh, const __half* __restrict__ Bl,
    const float* __restrict__ bias,
    __half* __restrict__ O1, __half* __restrict__ O2,
    float* __restrict__ Cout, int mode)
{
    extern __shared__ char dynsmem[];
    uint32_t sbase = smem_u32(dynsmem);
    int t = threadIdx.x;
    int wid = t >> 5, lane = t & 31;
    int wm = wid >> 3, wn = wid & 7;

    int arow0, brow0, m0;
    if (mode < 2) {
        arow0 = blockIdx.x * 128; brow0 = blockIdx.y * 128; m0 = arow0;
    } else {
        arow0 = RQ + blockIdx.z * 512 + blockIdx.x * 128;
        brow0 = blockIdx.z * 512 + blockIdx.y * 128;
        m0 = blockIdx.x * 128;
    }

    const __half* srcp[2];
    uint32_t dstoff[2];
#pragma unroll
    for (int j = 0; j < 2; j++) {
        int idx = t + 512 * j;
        int arr = idx >> 8;
        int rem = idx & 255;
        int row = rem >> 1, seg = rem & 1;
        const __half* pl = (arr == 0) ? Ah : (arr == 1) ? Al : (arr == 2) ? Bh : Bl;
        int grow = ((arr < 2) ? arow0 : brow0) + row;
        srcp[j] = pl + (size_t)grow * DD + seg * 8;
        dstoff[j] = (uint32_t)(arr * 6144 + row * 48 + seg * 16);
    }

    float acc[4][2][4];
#pragma unroll
    for (int mt = 0; mt < 4; mt++)
#pragma unroll
        for (int nt = 0; nt < 2; nt++)
#pragma unroll
            for (int v = 0; v < 4; v++) acc[mt][nt][v] = 0.f;

#pragma unroll
    for (int j = 0; j < 2; j++) cpasync16(sbase + dstoff[j], srcp[j]);
    CP_COMMIT;

    uint32_t aAddrBase = (uint32_t)((wm * 64 + (lane & 15)) * 48 + ((lane >> 4) & 1) * 16);
    uint32_t bAddrBase = (uint32_t)(12288 +
        (wn * 16 + (lane & 7) + ((lane >> 4) & 1) * 8) * 48 + ((lane >> 3) & 1) * 16);

#pragma unroll 1
    for (int kc = 0; kc < 16; kc++) {
        if (kc < 15) {
            uint32_t sdst = sbase + ((kc + 1) & 1) * STG_SZ;
#pragma unroll
            for (int j = 0; j < 2; j++)
                cpasync16(sdst + dstoff[j], srcp[j] + (kc + 1) * 16);
            CP_COMMIT;
            CP_WAIT1;
        } else {
            CP_WAIT0;
        }
        __syncthreads();

        uint32_t stg = sbase + (kc & 1) * STG_SZ;
        uint32_t bh[4], bl[4];
        ldsm4(bh[0], bh[1], bh[2], bh[3], stg + bAddrBase);
        ldsm4(bl[0], bl[1], bl[2], bl[3], stg + bAddrBase + 6144);

#pragma unroll
        for (int mt = 0; mt < 4; mt++) {
            uint32_t a_h[4], a_l[4];
            uint32_t aa = stg + aAddrBase + (uint32_t)(mt * 16 * 48);
            ldsm4(a_h[0], a_h[1], a_h[2], a_h[3], aa);
            ldsm4(a_l[0], a_l[1], a_l[2], a_l[3], aa + 6144);
#pragma unroll
            for (int nt = 0; nt < 2; nt++) {
                float* d = acc[mt][nt];
                mma16816h(d, a_h, bh[nt * 2], bh[nt * 2 + 1]);
                mma16816h(d, a_h, bl[nt * 2], bl[nt * 2 + 1]);
                mma16816h(d, a_l, bh[nt * 2], bh[nt * 2 + 1]);
            }
        }
        __syncthreads();
    }

    float* sT = (float*)dynsmem;
#pragma unroll
    for (int mt = 0; mt < 4; mt++)
#pragma unroll
        for (int nt = 0; nt < 2; nt++)
#pragma unroll
            for (int v = 0; v < 4; v++) {
                int n = wn * 16 + nt * 8 + (lane & 3) * 2 + (v & 1);
                int m = wm * 64 + mt * 16 + (lane >> 2) + ((v & 2) ? 8 : 0);
                sT[n * 132 + m] = acc[mt][nt][v];
            }
    __syncthreads();

#pragma unroll 1
    for (int rr = 0; rr < 8; rr++) {
        int n = wid * 8 + rr;
        float4 v4 = *(float4*)&sT[n * 132 + lane * 4];
        float vv[4] = {v4.x, v4.y, v4.z, v4.w};
        int gn = brow0 + n;
        if (mode < 2) {
            float nrm = 0.f;
            unsigned short h[4], lo[4];
#pragma unroll
            for (int j = 0; j < 4; j++) {
                float v = vv[j] + bias[m0 + lane * 4 + j];
                if (mode == 0) v = fmaxf(v, 0.f);
                else nrm += v * v;
                __half hh_ = __float2half_rn(v);
                float r1 = v - __half2float(hh_);
                __half ll_ = __float2half_rn(r1);
                h[j] = *(unsigned short*)&hh_;
                lo[j] = *(unsigned short*)&ll_;
            }
            size_t ob = (size_t)gn * DD + m0 + lane * 4;
            *(uint2*)&O1[ob] = *(uint2*)h;
            *(uint2*)&O2[ob] = *(uint2*)lo;
            if (mode == 1) {
#pragma unroll
                for (int o = 16; o; o >>= 1) nrm += __shfl_xor_sync(~0u, nrm, o);
                if (lane == 0) {
                    if (gn < RQ) atomicAdd(&g_q2[gn], nrm);
                    else         atomicAdd(&g_r2[gn - RQ], nrm);
                }
            }
        } else {
            float q2v = g_q2[gn];
            int rbase = blockIdx.z * 512 + m0 + lane * 4;
            float4 o;
            o.x = sqrtf(fmaxf(q2v + g_r2[rbase + 0] - 2.f * vv[0], 1e-6f));
            o.y = sqrtf(fmaxf(q2v + g_r2[rbase + 1] - 2.f * vv[1], 1e-6f));
            o.z = sqrtf(fmaxf(q2v + g_r2[rbase + 2] - 2.f * vv[2], 1e-6f));
            o.w = sqrtf(fmaxf(q2v + g_r2[rbase + 3] - 2.f * vv[3], 1e-6f));
            *(float4*)&Cout[(size_t)gn * 512 + m0 + lane * 4] = o;
        }
    }
}

// ---------------- prep: logmu/lognu, zero buffers ----------------
__global__ void __launch_bounds__(512) prep_kernel(const float* __restrict__ mq,
                                                   const float* __restrict__ mr) {
    __shared__ float red[512];
    int b = blockIdx.x, t = threadIdx.x;
    float vq = mq[b * 512 + t];
    red[t] = vq; __syncthreads();
    for (int s = 256; s; s >>= 1) { if (t < s) red[t] += red[t + s]; __syncthreads(); }
    float smq = red[0]; __syncthreads();
    g_logmu[b * 512 + t] = logf(fmaxf(vq / (smq + 1e-8f), 1e-8f));

    float vr = mr[b * 512 + t];
    red[t] = vr; __syncthreads();
    for (int s = 256; s; s >>= 1) { if (t < s) red[t] += red[t + s]; __syncthreads(); }
    float smr = red[0]; __syncthreads();
    g_lognu[b * 512 + t] = logf(fmaxf(vr / (smr + 1e-8f), 1e-8f));

    g_q2[b * 512 + t] = 0.f;
    g_r2[b * 512 + t] = 0.f;
    if (t == 0) g_cvec[b] = 0.f;
}

// ============================================================================
// Fused Sinkhorn (single E-sweep, R15) with peeled fused ebuild. (passing)
// ============================================================================
__global__ void __launch_bounds__(256, 1) __cluster_dims__(4, 1, 1)
sinkhorn_cluster(const float* __restrict__ C) {
    __shared__ __align__(16) float s_vb[512];
    __shared__ __align__(16) float s_nu[512];
    __shared__ float s_partial[512];
    __shared__ float s_lb[512];
    __shared__ float s_g[128];
    __shared__ float s_rm[128];
    __shared__ float s_red[256];
    __shared__ float s_locmax;

    int bat = blockIdx.x >> 2;
    int rank = blockIdx.x & 3;
    int t = threadIdx.x;
    int wid = t >> 5, lane = t & 31;
    int rowbase = bat * 512 + rank * 128;
    float* Eb = g_E + (size_t)rowbase * 512;
    const float* Cb = C + (size_t)rowbase * 512;

    s_nu[t]       = g_lognu[bat * 512 + t];
    s_nu[t + 256] = g_lognu[bat * 512 + 256 + t];
    s_partial[t] = 0.f; s_partial[t + 256] = 0.f;
    __syncthreads();

    // ======== peeled iteration 0 (fused ebuild; sb=0, vb=1, sa_prev=0) ======
    {
        float colacc[16];
#pragma unroll
        for (int j = 0; j < 16; j++) colacc[j] = 0.f;
        float gmaxloc = -1e30f;

#pragma unroll 1
        for (int rr = wid; rr < 128; rr += 8) {
            const float4* Cr = (const float4*)(Cb + (size_t)rr * 512);
            float4 ev[4];
            float rm = -1e30f;
#pragma unroll
            for (int c = 0; c < 4; c++) {
                float4 cc = Cr[lane + 32 * c];
                float4 nu = ((const float4*)s_nu)[lane + 32 * c];
                float4 v;
                v.x = fmaf(cc.x, -20.f, nu.x);
                v.y = fmaf(cc.y, -20.f, nu.y);
                v.z = fmaf(cc.z, -20.f, nu.z);
                v.w = fmaf(cc.w, -20.f, nu.w);
                ev[c] = v;
                rm = fmaxf(rm, fmaxf(fmaxf(v.x, v.y), fmaxf(v.z, v.w)));
            }
#pragma unroll
            for (int o = 16; o; o >>= 1) rm = fmaxf(rm, __shfl_xor_sync(~0u, rm, o));
            float4* Er = (float4*)(Eb + (size_t)rr * 512);
            float acc = 0.f;
#pragma unroll
            for (int c = 0; c < 4; c++) {
                float4 e;
                e.x = fexp(ev[c].x - rm); e.y = fexp(ev[c].y - rm);
                e.z = fexp(ev[c].z - rm); e.w = fexp(ev[c].w - rm);
                ev[c] = e;
                Er[lane + 32 * c] = e;
                acc += e.x + e.y + e.z + e.w;
            }
#pragma unroll
            for (int o = 16; o; o >>= 1) acc += __shfl_xor_sync(~0u, acc, o);
            float g = -logf(fmaxf(acc, 1e-35f));
            if (lane == 0) {
                s_g[rr] = g;
                s_rm[rr] = rm;
                g_rowRef[rowbase + rr] = rm;
            }
            gmaxloc = fmaxf(gmaxloc, g);
            float wa = fexp(g);
#pragma unroll
            for (int c = 0; c < 4; c++) {
                colacc[c * 4 + 0] = fmaf(ev[c].x, wa, colacc[c * 4 + 0]);
                colacc[c * 4 + 1] = fmaf(ev[c].y, wa, colacc[c * 4 + 1]);
                colacc[c * 4 + 2] = fmaf(ev[c].z, wa, colacc[c * 4 + 2]);
                colacc[c * 4 + 3] = fmaf(ev[c].w, wa, colacc[c * 4 + 3]);
            }
        }
#pragma unroll
        for (int c = 0; c < 4; c++) {
            int m = (lane + 32 * c) * 4;
            atomicAdd(&s_partial[m + 0], colacc[c * 4 + 0]);
            atomicAdd(&s_partial[m + 1], colacc[c * 4 + 1]);
            atomicAdd(&s_partial[m + 2], colacc[c * 4 + 2]);
            atomicAdd(&s_partial[m + 3], colacc[c * 4 + 3]);
        }
        s_red[t] = gmaxloc;
        __syncthreads();
        for (int s = 128; s; s >>= 1) { if (t < s) s_red[t] = fmaxf(s_red[t], s_red[t + s]); __syncthreads(); }
        if (t == 0) s_locmax = s_red[0];
        __syncthreads();
        cluster_sync_();   // publish partials + locmax
    }

    float sa_prev = -1e30f;
    {
        uint32_t lmaddr = smem_u32(&s_locmax);
#pragma unroll
        for (int r = 0; r < 4; r++) sa_prev = fmaxf(sa_prev, dsmem_ld_f(lmaddr, r));
#pragma unroll
        for (int cg = 0; cg < 2; cg++) {
            int col = t + cg * 256;
            uint32_t pa = smem_u32(&s_partial[col]);
            float s = 0.f;
#pragma unroll
            for (int r = 0; r < 4; r++) s += dsmem_ld_f(pa, r);
            s_lb[col] = -(0.f + logf(fmaxf(s, 1e-35f)));
        }
        __syncthreads();
        cluster_sync_();   // remote reads done
    }

    // ======== main loop it = 1..14 ====================
    for (int it = 1; it < NI; it++) {
        s_red[t] = fmaxf(s_lb[t], s_lb[t + 256]);
        __syncthreads();
        for (int s = 128; s; s >>= 1) { if (t < s) s_red[t] = fmaxf(s_red[t], s_red[t + s]); __syncthreads(); }
        float sb = s_red[0];
        __syncthreads();
        s_vb[t]       = fexp(s_lb[t] - sb);
        s_vb[t + 256] = fexp(s_lb[t + 256] - sb);
        s_partial[t] = 0.f; s_partial[t + 256] = 0.f;
        __syncthreads();

        float colacc[16];
#pragma unroll
        for (int j = 0; j < 16; j++) colacc[j] = 0.f;
        float gmaxloc = -1e30f;

#pragma unroll 1
        for (int rr = wid; rr < 128; rr += 8) {
            const float4* Er = (const float4*)(Eb + (size_t)rr * 512);
            const float4* V  = (const float4*)s_vb;
            float4 ev[4];
            float acc = 0.f;
#pragma unroll
            for (int c = 0; c < 4; c++) {
                ev[c] = Er[lane + 32 * c];
                float4 v = V[lane + 32 * c];
                acc += ev[c].x * v.x + ev[c].y * v.y + ev[c].z * v.z + ev[c].w * v.w;
            }
#pragma unroll
            for (int o = 16; o; o >>= 1) acc += __shfl_xor_sync(~0u, acc, o);
            float g = -(sb + logf(fmaxf(acc, 1e-35f)));
            if (lane == 0) s_g[rr] = g;
            gmaxloc = fmaxf(gmaxloc, g);
            float wa = fexp(g - sa_prev);
#pragma unroll
            for (int c = 0; c < 4; c++) {
                colacc[c * 4 + 0] = fmaf(ev[c].x, wa, colacc[c * 4 + 0]);
                colacc[c * 4 + 1] = fmaf(ev[c].y, wa, colacc[c * 4 + 1]);
                colacc[c * 4 + 2] = fmaf(ev[c].z, wa, colacc[c * 4 + 2]);
                colacc[c * 4 + 3] = fmaf(ev[c].w, wa, colacc[c * 4 + 3]);
            }
        }
#pragma unroll
        for (int c = 0; c < 4; c++) {
            int m = (lane + 32 * c) * 4;
            atomicAdd(&s_partial[m + 0], colacc[c * 4 + 0]);
            atomicAdd(&s_partial[m + 1], colacc[c * 4 + 1]);
            atomicAdd(&s_partial[m + 2], colacc[c * 4 + 2]);
            atomicAdd(&s_partial[m + 3], colacc[c * 4 + 3]);
        }
        s_red[t] = gmaxloc;
        __syncthreads();
        for (int s = 128; s; s >>= 1) { if (t < s) s_red[t] = fmaxf(s_red[t], s_red[t + s]); __syncthreads(); }
        if (t == 0) s_locmax = s_red[0];
        __syncthreads();
        cluster_sync_();   // publish partials + locmax

        float sa_new = -1e30f;
        uint32_t lmaddr = smem_u32(&s_locmax);
#pragma unroll
        for (int r = 0; r < 4; r++) sa_new = fmaxf(sa_new, dsmem_ld_f(lmaddr, r));

#pragma unroll
        for (int cg = 0; cg < 2; cg++) {
            int col = t + cg * 256;
            uint32_t pa = smem_u32(&s_partial[col]);
            float s = 0.f;
#pragma unroll
            for (int r = 0; r < 4; r++) s += dsmem_ld_f(pa, r);
            s_lb[col] = -(sa_prev + logf(fmaxf(s, 1e-35f)));
        }
        __syncthreads();
        cluster_sync_();   // remote reads done
        sa_prev = sa_new;
    }

    if (t < 128)
        g_la[rowbase + t] = s_g[t] - (g_logmu[rowbase + t] + s_rm[t]);
    if (rank == 0) {
        g_lb[bat * 512 + t]       = s_lb[t];
        g_lb[bat * 512 + 256 + t] = s_lb[t + 256];
    }
    cluster_sync_();
}

// ============================================================================
// Single-kernel MI chain: cluster of 8 CTAs per batch (each owns 64 rows),
// T resident in GMEM (smem stays ~6KB -> high occupancy, unlike R13).
// Colsums exchanged via DSMEM publish/consume double-sync each pass.
// pass0: T0 = rownorm((E*ra*rb)^2); pass1,2: T = rownorm((T*inv)^2);
// final: T = T*inv, c += sum(T*C).
// ============================================================================
__global__ void __launch_bounds__(256, 1) __cluster_dims__(8, 1, 1)
mi_all(float* __restrict__ T, const float* __restrict__ C) {
    __shared__ float s_rb[512];
    __shared__ float s_part[512];
    __shared__ float s_inv[512];
    __shared__ float s_red[8];

    int bat = blockIdx.x >> 3;
    int rank = blockIdx.x & 7;
    int t = threadIdx.x, wid = t >> 5, lane = t & 31;
    int rowbase = bat * 512 + rank * 64;
    const float* Eb = g_E + (size_t)rowbase * 512;
    float* Tb = T + (size_t)rowbase * 512;
    const float* Cb = C + (size_t)rowbase * 512;

    s_rb[t]       = fexp(g_lb[bat * 512 + t]);
    s_rb[t + 256] = fexp(g_lb[bat * 512 + 256 + t]);
    s_part[t] = 0.f; s_part[t + 256] = 0.f;
    __syncthreads();

    // ---- pass 0 ----
    {
        float colacc[16];
#pragma unroll
        for (int j = 0; j < 16; j++) colacc[j] = 0.f;
#pragma unroll 1
        for (int rr = wid; rr < 64; rr += 8) {
            int k = rowbase + rr;
            float ra = fexp(g_logmu[k] + g_rowRef[k] + g_la[k]);
            const float4* Er = (const float4*)(Eb + (size_t)rr * 512);
            float4* Tr = (float4*)(Tb + (size_t)rr * 512);
            float4 xv[4];
            float rs = 0.f;
#pragma unroll
            for (int c = 0; c < 4; c++) {
                float4 e  = Er[lane + 32 * c];
                float4 r4 = ((const float4*)s_rb)[lane + 32 * c];
                float4 x;
                x.x = e.x * ra * r4.x; x.y = e.y * ra * r4.y;
                x.z = e.z * ra * r4.z; x.w = e.w * ra * r4.w;
                x.x *= x.x; x.y *= x.y; x.z *= x.z; x.w *= x.w;
                xv[c] = x;
                rs += x.x + x.y + x.z + x.w;
            }
#pragma unroll
            for (int o = 16; o; o >>= 1) rs += __shfl_xor_sync(~0u, rs, o);
            float inv = 1.0f / (rs + 1e-8f);
#pragma unroll
            for (int c = 0; c < 4; c++) {
                float4 x = xv[c];
                x.x *= inv; x.y *= inv; x.z *= inv; x.w *= inv;
                Tr[lane + 32 * c] = x;
                colacc[c * 4 + 0] += x.x; colacc[c * 4 + 1] += x.y;
                colacc[c * 4 + 2] += x.z; colacc[c * 4 + 3] += x.w;
            }
        }
#pragma unroll
        for (int c = 0; c < 4; c++) {
            int m = (lane + 32 * c) * 4;
            atomicAdd(&s_part[m + 0], colacc[c * 4 + 0]);
            atomicAdd(&s_part[m + 1], colacc[c * 4 + 1]);
            atomicAdd(&s_part[m + 2], colacc[c * 4 + 2]);
            atomicAdd(&s_part[m + 3], colacc[c * 4 + 3]);
        }
        __syncthreads();
        cluster_sync_();             // publish partials
#pragma unroll
        for (int cg = 0; cg < 2; cg++) {
            int col = t + cg * 256;
            uint32_t pa = smem_u32(&s_part[col]);
            float s = 0.f;
#pragma unroll
            for (int r = 0; r < 8; r++) s += dsmem_ld_f(pa, r);
            s_inv[col] = 1.0f / (s + 1e-8f);
        }
        __syncthreads();
        cluster_sync_();             // remote reads done
    }

    // ---- passes 1..2 ----
#pragma unroll 1
    for (int it = 1; it <= 2; it++) {
        s_part[t] = 0.f; s_part[t + 256] = 0.f;
        float colacc[16];
#pragma unroll
        for (int j = 0; j < 16; j++) colacc[j] = 0.f;
        __syncthreads();
#pragma unroll 1
        for (int rr = wid; rr < 64; rr += 8) {
            float4* Tr = (float4*)(Tb + (size_t)rr * 512);
            float4 xv[4];
            float rs = 0.f;
#pragma unroll
            for (int c = 0; c < 4; c++) {
                float4 x  = Tr[lane + 32 * c];
                float4 iv = ((const float4*)s_inv)[lane + 32 * c];
                x.x *= iv.x; x.y *= iv.y; x.z *= iv.z; x.w *= iv.w;
                x.x *= x.x; x.y *= x.y; x.z *= x.z; x.w *= x.w;
                xv[c] = x;
                rs += x.x + x.y + x.z + x.w;
            }
#pragma unroll
            for (int o = 16; o; o >>= 1) rs += __shfl_xor_sync(~0u, rs, o);
            float rinv = 1.0f / (rs + 1e-8f);
#pragma unroll
            for (int c = 0; c < 4; c++) {
                float4 x = xv[c];
                x.x *= rinv; x.y *= rinv; x.z *= rinv; x.w *= rinv;
                Tr[lane + 32 * c] = x;
                colacc[c * 4 + 0] += x.x; colacc[c * 4 + 1] += x.y;
                colacc[c * 4 + 2] += x.z; colacc[c * 4 + 3] += x.w;
            }
        }
#pragma unroll
        for (int c = 0; c < 4; c++) {
            int m = (lane + 32 * c) * 4;
            atomicAdd(&s_part[m + 0], colacc[c * 4 + 0]);
            atomicAdd(&s_part[m + 1], colacc[c * 4 + 1]);
            atomicAdd(&s_part[m + 2], colacc[c * 4 + 2]);
            atomicAdd(&s_part[m + 3], colacc[c * 4 + 3]);
        }
        __syncthreads();
        cluster_sync_();             // publish partials
#pragma unroll
        for (int cg = 0; cg < 2; cg++) {
            int col = t + cg * 256;
            uint32_t pa = smem_u32(&s_part[col]);
            float s = 0.f;
#pragma unroll
            for (int r = 0; r < 8; r++) s += dsmem_ld_f(pa, r);
            s_inv[col] = 1.0f / (s + 1e-8f);
        }
        __syncthreads();
        cluster_sync_();             // remote reads done
    }

    // ---- final: T = T*inv; c += sum(T*C) ----
    float cacc = 0.f;
#pragma unroll 1
    for (int rr = wid; rr < 64; rr += 8) {
        float4* Tr = (float4*)(Tb + (size_t)rr * 512);
        const float4* Cr = (const float4*)(Cb + (size_t)rr * 512);
#pragma unroll
        for (int c = 0; c < 4; c++) {
            float4 x  = Tr[lane + 32 * c];
            float4 iv = ((const float4*)s_inv)[lane + 32 * c];
            x.x *= iv.x; x.y *= iv.y; x.z *= iv.z; x.w *= iv.w;
            Tr[lane + 32 * c] = x;
            float4 cc = Cr[lane + 32 * c];
            cacc += x.x * cc.x + x.y * cc.y + x.z * cc.z + x.w * cc.w;
        }
    }
#pragma unroll
    for (int o = 16; o; o >>= 1) cacc += __shfl_xor_sync(~0u, cacc, o);
    if (lane == 0) s_red[wid] = cacc;
    __syncthreads();
    if (t == 0) {
        float s = 0.f;
#pragma unroll
        for (int w = 0; w < 8; w++) s += s_red[w];
        atomicAdd(&g_cvec[bat], s);
    }
    cluster_sync_();                 // exit guard
}

// ---------------- finalize ----------------
__global__ void finalize_kernel(float* __restrict__ sim, float* __restrict__ outc) {
    int b = threadIdx.x;
    if (b < BB) {
        float c = g_cvec[b];
        outc[b] = c;
        sim[b] = 1.0f / (1.0f + expf(c));
    }
}

// ---------------- launch ----------------
extern "C" void kernel_launch(void* const* d_in, const int* in_sizes, int n_in,
                              void* d_out, int out_size) {
    const float* sq = (const float*)d_in[0];
    const float* sr = (const float*)d_in[1];
    const float* mq = (const float*)d_in[2];
    const float* mr = (const float*)d_in[3];
    const float* W1 = (const float*)d_in[4];
    const float* b1 = (const float*)d_in[5];
    const float* W2 = (const float*)d_in[6];
    const float* b2 = (const float*)d_in[7];

    float* out = (float*)d_out;
    float* out_sim = out;
    float* out_T   = out + BB;
    float* out_C   = out + BB + TOTE;
    float* out_c   = out + BB + 2 * TOTE;

    __half *Xh, *Xl, *Hh, *Hl, *Ph, *Pl, *W1h, *W1l, *W2h, *W2l;
    cudaGetSymbolAddress((void**)&Xh, g_Xh);  cudaGetSymbolAddress((void**)&Xl, g_Xl);
    cudaGetSymbolAddress((void**)&Hh, g_Hh);  cudaGetSymbolAddress((void**)&Hl, g_Hl);
    cudaGetSymbolAddress((void**)&Ph, g_Ph);  cudaGetSymbolAddress((void**)&Pl, g_Pl);
    cudaGetSymbolAddress((void**)&W1h, g_W1h); cudaGetSymbolAddress((void**)&W1l, g_W1l);
    cudaGetSymbolAddress((void**)&W2h, g_W2h); cudaGetSymbolAddress((void**)&W2l, g_W2l);

    cudaFuncSetAttribute(gemm_mma, cudaFuncAttributeMaxDynamicSharedMemorySize, DYN_SZ);

    prep_kernel<<<BB, 512>>>(mq, mr);

    int n4x = (RQ * DD) / 4;
    split2_kernel<<<(n4x + 255) / 256, 256>>>(sq, Xh, Xl, n4x);
    split2_kernel<<<(n4x + 255) / 256, 256>>>(sr, Xh + (size_t)RQ * DD,
                                              Xl + (size_t)RQ * DD, n4x);
    int n4w = (DD * DD) / 4;
    split2_kernel<<<(n4w + 255) / 256, 256>>>(W1, W1h, W1l, n4w);
    split2_kernel<<<(n4w + 255) / 256, 256>>>(W2, W2h, W2l, n4w);

    // layer 1: H = relu(X @ W1^T + b1)
    gemm_mma<<<dim3(2, RTOT / 128), 512, DYN_SZ>>>(
        W1h, W1l, Xh, Xl, b1, Hh, Hl, nullptr, 0);
    // layer 2: P = H @ W2^T + b2 (+ row norms)
    gemm_mma<<<dim3(2, RTOT / 128), 512, DYN_SZ>>>(
        W2h, W2l, Hh, Hl, b2, Ph, Pl, nullptr, 1);
    // cross distances
    gemm_mma<<<dim3(4, 4, BB), 512, DYN_SZ>>>(
        Ph, Pl, Ph, Pl, nullptr, nullptr, nullptr, out_C, 2);

    // Sinkhorn with peeled fused ebuild (iter 0 builds E from C)
    sinkhorn_cluster<<<BB * 4, 256>>>(out_C);

    // fused MI chain (T in gmem, colsums via DSMEM)
    mi_all<<<BB * 8, 256>>>(out_T, out_C);

    finalize_kernel<<<1, 64>>>(out_sim, out_c);
}